// round 3
// baseline (speedup 1.0000x reference)
#include <cuda_runtime.h>
#include <cstdint>

// Problem constants
#define NB   16384
#define NS   37
#define NF   17
#define NOWN 9
#define NH   256
#define NE   128
#define NOUT 23

// scratch: pooled encoder output per batch row (written fully by kernel 1)
__device__ float g_summed[(size_t)NB * NE];

// ---------------------------------------------------------------------------
// packed fp32x2 FMA (sm_103a FFMA2) — identical rounding to two fmaf's
// ---------------------------------------------------------------------------
__device__ __forceinline__ float2 ffma2(float2 a, float2 b, float2 c) {
    union U { float2 f; unsigned long long u; } A, B, C, D;
    A.f = a; B.f = b; C.f = c;
    asm("fma.rn.f32x2 %0, %1, %2, %3;" : "=l"(D.u) : "l"(A.u), "l"(B.u), "l"(C.u));
    return D.f;
}

// ===========================================================================
// Kernel 1: per-batch token encoder.
// One block per batch element b. 256 threads (tx = lane, ty = warp).
// Rows: M = 40 (37 real tokens + 3 zero rows; rows are independent through
// the MLP, and padded rows get mask = 0 so they never enter the pooled sum).
// Thread tile: 5 rows (ty + 8i) x 8 cols (as 4 float2: 2*(tx+32j)).
// ===========================================================================
__global__ void __launch_bounds__(256, 2)
seq_kernel(const float* __restrict__ obs,
           const float* __restrict__ W1, const float* __restrict__ b1,
           const float* __restrict__ W2, const float* __restrict__ b2,
           const float* __restrict__ W3, const float* __restrict__ b3)
{
    extern __shared__ float sm[];
    float* Xs   = sm;                 // 40*32   = 1280
    float* Hs   = Xs  + 40 * 32;      // 40*260  = 10400
    float* Ws   = Hs  + 40 * 260;     // 32*256  = 8192
    float* Msk  = Ws  + 32 * 256;     // 40
    float* Part = Msk + 40;           // 8*128   = 1024   (total 20936 floats)

    const int tid = threadIdx.x;
    const int tx  = tid & 31;
    const int ty  = tid >> 5;
    const int b   = blockIdx.x;

    // ---- load X tile (37 x 17, padded to 40 x 32 with zeros) ----
    const float* xg = obs + ((size_t)b * 38 + 1) * NF;
    for (int e = tid; e < 40 * 32; e += 256) {
        int r = e >> 5, c = e & 31;
        Xs[e] = (r < NS && c < NF) ? xg[r * NF + c] : 0.f;
    }
    __syncthreads();

    // ---- mask[r] = (sum |x| != 0) ----
    if (tid < 40) {
        float s = 0.f;
        #pragma unroll
        for (int c = 0; c < NF; ++c) s += fabsf(Xs[tid * 32 + c]);
        Msk[tid] = (s != 0.f) ? 1.f : 0.f;
    }

    // =============== Layer 1: H1 = relu(X @ W1 + b1), K=32 (17 real) =======
    float2 acc[5][4];
    #pragma unroll
    for (int j = 0; j < 4; ++j) {
        float2 bv = __ldg(((const float2*)b1) + tx + 32 * j);
        #pragma unroll
        for (int i = 0; i < 5; ++i) acc[i][j] = bv;
    }
    for (int i = 0; i < 32; ++i)
        Ws[i * 256 + tid] = (i < NF) ? __ldg(&W1[i * 256 + tid]) : 0.f;
    __syncthreads();

    #pragma unroll 8
    for (int kk = 0; kk < 32; ++kk) {
        float a[5];
        #pragma unroll
        for (int i = 0; i < 5; ++i) a[i] = Xs[(ty + 8 * i) * 32 + kk];
        #pragma unroll
        for (int j = 0; j < 4; ++j) {
            float2 w = *(const float2*)(Ws + kk * 256 + 2 * (tx + 32 * j));
            #pragma unroll
            for (int i = 0; i < 5; ++i)
                acc[i][j] = ffma2(make_float2(a[i], a[i]), w, acc[i][j]);
        }
    }
    __syncthreads();
    #pragma unroll
    for (int i = 0; i < 5; ++i) {
        int r = ty + 8 * i;
        #pragma unroll
        for (int j = 0; j < 4; ++j) {
            float2 v = acc[i][j];
            v.x = fmaxf(v.x, 0.f); v.y = fmaxf(v.y, 0.f);
            *(float2*)(Hs + r * 260 + 2 * (tx + 32 * j)) = v;
        }
    }

    // =============== Layer 2: H2 = relu(H1 @ W2 + b2), K=256 ===============
    #pragma unroll
    for (int j = 0; j < 4; ++j) {
        float2 bv = __ldg(((const float2*)b2) + tx + 32 * j);
        #pragma unroll
        for (int i = 0; i < 5; ++i) acc[i][j] = bv;
    }
    for (int cch = 0; cch < 8; ++cch) {
        __syncthreads();
        for (int i = 0; i < 32; ++i)
            Ws[i * 256 + tid] = __ldg(&W2[(cch * 32 + i) * 256 + tid]);
        __syncthreads();
        #pragma unroll 8
        for (int kk = 0; kk < 32; ++kk) {
            float a[5];
            #pragma unroll
            for (int i = 0; i < 5; ++i) a[i] = Hs[(ty + 8 * i) * 260 + cch * 32 + kk];
            #pragma unroll
            for (int j = 0; j < 4; ++j) {
                float2 w = *(const float2*)(Ws + kk * 256 + 2 * (tx + 32 * j));
                #pragma unroll
                for (int i = 0; i < 5; ++i)
                    acc[i][j] = ffma2(make_float2(a[i], a[i]), w, acc[i][j]);
            }
        }
    }
    __syncthreads();
    #pragma unroll
    for (int i = 0; i < 5; ++i) {
        int r = ty + 8 * i;
        #pragma unroll
        for (int j = 0; j < 4; ++j) {
            float2 v = acc[i][j];
            v.x = fmaxf(v.x, 0.f); v.y = fmaxf(v.y, 0.f);
            *(float2*)(Hs + r * 260 + 2 * (tx + 32 * j)) = v;
        }
    }

    // =============== Layer 3: H3 = relu(H2 @ W3 + b3), N=128 ===============
    float2 acc3[5][2];
    #pragma unroll
    for (int j = 0; j < 2; ++j) {
        float2 bv = __ldg(((const float2*)b3) + tx + 32 * j);
        #pragma unroll
        for (int i = 0; i < 5; ++i) acc3[i][j] = bv;
    }
    for (int cch = 0; cch < 8; ++cch) {
        __syncthreads();
        for (int i = 0; i < 16; ++i) {
            int e = tid + 256 * i;
            Ws[e] = __ldg(&W3[cch * 32 * 128 + e]);
        }
        __syncthreads();
        #pragma unroll 8
        for (int kk = 0; kk < 32; ++kk) {
            float a[5];
            #pragma unroll
            for (int i = 0; i < 5; ++i) a[i] = Hs[(ty + 8 * i) * 260 + cch * 32 + kk];
            #pragma unroll
            for (int j = 0; j < 2; ++j) {
                float2 w = *(const float2*)(Ws + kk * 128 + 2 * (tx + 32 * j));
                #pragma unroll
                for (int i = 0; i < 5; ++i)
                    acc3[i][j] = ffma2(make_float2(a[i], a[i]), w, acc3[i][j]);
            }
        }
    }

    // ---- masked relu + partial pooled sum over this thread's 5 rows ----
    float2 ps[2];
    ps[0] = make_float2(0.f, 0.f); ps[1] = make_float2(0.f, 0.f);
    #pragma unroll
    for (int i = 0; i < 5; ++i) {
        float m = Msk[ty + 8 * i];
        #pragma unroll
        for (int j = 0; j < 2; ++j) {
            float2 v = acc3[i][j];
            ps[j].x += m * fmaxf(v.x, 0.f);
            ps[j].y += m * fmaxf(v.y, 0.f);
        }
    }
    #pragma unroll
    for (int j = 0; j < 2; ++j)
        *(float2*)(Part + ty * 128 + 2 * (tx + 32 * j)) = ps[j];
    __syncthreads();
    if (tid < 128) {
        float s = 0.f;
        #pragma unroll
        for (int t = 0; t < 8; ++t) s += Part[t * 128 + tid];
        g_summed[(size_t)b * NE + tid] = s;
    }
}

// ===========================================================================
// Kernel 2: actor + value heads, fused. 32 rows per block, 256 threads.
// cat = [summed(128) | own(9) | zero-pad to 160].
// Thread tile: 4 rows (ty + 8i) x 8 cols (4 float2).
// ===========================================================================
__global__ void __launch_bounds__(256, 2)
head_kernel(const float* __restrict__ obs,
            const float* __restrict__ aW1, const float* __restrict__ ab1,
            const float* __restrict__ aW2, const float* __restrict__ ab2,
            const float* __restrict__ aW3, const float* __restrict__ ab3,
            const float* __restrict__ vW1, const float* __restrict__ vb1,
            const float* __restrict__ vW2, const float* __restrict__ vb2,
            const float* __restrict__ vW3, const float* __restrict__ vb3,
            float* __restrict__ out)
{
    extern __shared__ float sm[];
    float* Cs = sm;              // 32*160 = 5120
    float* Hs = Cs + 32 * 160;   // 32*260 = 8320
    float* Ws = Hs + 32 * 260;   // 32*256 = 8192  (total 21632 floats)

    const int tid = threadIdx.x;
    const int tx  = tid & 31;
    const int ty  = tid >> 5;
    const int m0  = blockIdx.x * 32;

    // ---- build cat tile ----
    for (int e = tid; e < 32 * 160; e += 256) {
        int r = e / 160, c = e - r * 160;
        int row = m0 + r;
        float v = 0.f;
        if (c < NE)            v = g_summed[(size_t)row * NE + c];
        else if (c < NE + NOWN) v = __ldg(&obs[(size_t)row * 38 * NF + (c - NE)]);
        Cs[e] = v;
    }

    float2 acc[4][4];

    // ================= actor layer 1 (K=160, rows>=137 of W are zero) ======
    #pragma unroll
    for (int j = 0; j < 4; ++j) {
        float2 bv = __ldg(((const float2*)ab1) + tx + 32 * j);
        #pragma unroll
        for (int i = 0; i < 4; ++i) acc[i][j] = bv;
    }
    for (int cch = 0; cch < 5; ++cch) {
        __syncthreads();
        for (int i = 0; i < 32; ++i) {
            int k = cch * 32 + i;
            Ws[i * 256 + tid] = (k < NE + NOWN) ? __ldg(&aW1[k * 256 + tid]) : 0.f;
        }
        __syncthreads();
        #pragma unroll 8
        for (int kk = 0; kk < 32; ++kk) {
            float a[4];
            #pragma unroll
            for (int i = 0; i < 4; ++i) a[i] = Cs[(ty + 8 * i) * 160 + cch * 32 + kk];
            #pragma unroll
            for (int j = 0; j < 4; ++j) {
                float2 w = *(const float2*)(Ws + kk * 256 + 2 * (tx + 32 * j));
                #pragma unroll
                for (int i = 0; i < 4; ++i)
                    acc[i][j] = ffma2(make_float2(a[i], a[i]), w, acc[i][j]);
            }
        }
    }
    __syncthreads();
    #pragma unroll
    for (int i = 0; i < 4; ++i) {
        int r = ty + 8 * i;
        #pragma unroll
        for (int j = 0; j < 4; ++j) {
            float2 v = acc[i][j];
            v.x = fmaxf(v.x, 0.f); v.y = fmaxf(v.y, 0.f);
            *(float2*)(Hs + r * 260 + 2 * (tx + 32 * j)) = v;
        }
    }

    // ================= actor layer 2 (K=256) ===============================
    #pragma unroll
    for (int j = 0; j < 4; ++j) {
        float2 bv = __ldg(((const float2*)ab2) + tx + 32 * j);
        #pragma unroll
        for (int i = 0; i < 4; ++i) acc[i][j] = bv;
    }
    for (int cch = 0; cch < 8; ++cch) {
        __syncthreads();
        for (int i = 0; i < 32; ++i)
            Ws[i * 256 + tid] = __ldg(&aW2[(cch * 32 + i) * 256 + tid]);
        __syncthreads();
        #pragma unroll 8
        for (int kk = 0; kk < 32; ++kk) {
            float a[4];
            #pragma unroll
            for (int i = 0; i < 4; ++i) a[i] = Hs[(ty + 8 * i) * 260 + cch * 32 + kk];
            #pragma unroll
            for (int j = 0; j < 4; ++j) {
                float2 w = *(const float2*)(Ws + kk * 256 + 2 * (tx + 32 * j));
                #pragma unroll
                for (int i = 0; i < 4; ++i)
                    acc[i][j] = ffma2(make_float2(a[i], a[i]), w, acc[i][j]);
            }
        }
    }
    __syncthreads();
    #pragma unroll
    for (int i = 0; i < 4; ++i) {
        int r = ty + 8 * i;
        #pragma unroll
        for (int j = 0; j < 4; ++j) {
            float2 v = acc[i][j];
            v.x = fmaxf(v.x, 0.f); v.y = fmaxf(v.y, 0.f);
            *(float2*)(Hs + r * 260 + 2 * (tx + 32 * j)) = v;
        }
    }
    __syncthreads();

    // ================= logits = A2 @ aW3 + ab3  (N=23) =====================
    for (int e = tid; e < 256 * NOUT; e += 256) Ws[e] = __ldg(&aW3[e]);
    __syncthreads();
    if (tx < NOUT) {
        float accL[4];
        float bb = __ldg(&ab3[tx]);
        #pragma unroll
        for (int i = 0; i < 4; ++i) accL[i] = bb;
        for (int k = 0; k < 256; ++k) {
            float w = Ws[k * NOUT + tx];
            #pragma unroll
            for (int i = 0; i < 4; ++i) accL[i] += Hs[(ty + 8 * i) * 260 + k] * w;
        }
        #pragma unroll
        for (int i = 0; i < 4; ++i)
            out[(size_t)(m0 + ty + 8 * i) * NOUT + tx] = accL[i];
    }

    // ================= value layer 1 (K=160) ===============================
    #pragma unroll
    for (int j = 0; j < 4; ++j) {
        float2 bv = __ldg(((const float2*)vb1) + tx + 32 * j);
        #pragma unroll
        for (int i = 0; i < 4; ++i) acc[i][j] = bv;
    }
    for (int cch = 0; cch < 5; ++cch) {
        __syncthreads();
        for (int i = 0; i < 32; ++i) {
            int k = cch * 32 + i;
            Ws[i * 256 + tid] = (k < NE + NOWN) ? __ldg(&vW1[k * 256 + tid]) : 0.f;
        }
        __syncthreads();
        #pragma unroll 8
        for (int kk = 0; kk < 32; ++kk) {
            float a[4];
            #pragma unroll
            for (int i = 0; i < 4; ++i) a[i] = Cs[(ty + 8 * i) * 160 + cch * 32 + kk];
            #pragma unroll
            for (int j = 0; j < 4; ++j) {
                float2 w = *(const float2*)(Ws + kk * 256 + 2 * (tx + 32 * j));
                #pragma unroll
                for (int i = 0; i < 4; ++i)
                    acc[i][j] = ffma2(make_float2(a[i], a[i]), w, acc[i][j]);
            }
        }
    }
    __syncthreads();
    #pragma unroll
    for (int i = 0; i < 4; ++i) {
        int r = ty + 8 * i;
        #pragma unroll
        for (int j = 0; j < 4; ++j) {
            float2 v = acc[i][j];
            v.x = fmaxf(v.x, 0.f); v.y = fmaxf(v.y, 0.f);
            *(float2*)(Hs + r * 260 + 2 * (tx + 32 * j)) = v;
        }
    }

    // ================= value layer 2 (K=256) ===============================
    #pragma unroll
    for (int j = 0; j < 4; ++j) {
        float2 bv = __ldg(((const float2*)vb2) + tx + 32 * j);
        #pragma unroll
        for (int i = 0; i < 4; ++i) acc[i][j] = bv;
    }
    for (int cch = 0; cch < 8; ++cch) {
        __syncthreads();
        for (int i = 0; i < 32; ++i)
            Ws[i * 256 + tid] = __ldg(&vW2[(cch * 32 + i) * 256 + tid]);
        __syncthreads();
        #pragma unroll 8
        for (int kk = 0; kk < 32; ++kk) {
            float a[4];
            #pragma unroll
            for (int i = 0; i < 4; ++i) a[i] = Hs[(ty + 8 * i) * 260 + cch * 32 + kk];
            #pragma unroll
            for (int j = 0; j < 4; ++j) {
                float2 w = *(const float2*)(Ws + kk * 256 + 2 * (tx + 32 * j));
                #pragma unroll
                for (int i = 0; i < 4; ++i)
                    acc[i][j] = ffma2(make_float2(a[i], a[i]), w, acc[i][j]);
            }
        }
    }
    __syncthreads();
    #pragma unroll
    for (int i = 0; i < 4; ++i) {
        int r = ty + 8 * i;
        #pragma unroll
        for (int j = 0; j < 4; ++j) {
            float2 v = acc[i][j];
            v.x = fmaxf(v.x, 0.f); v.y = fmaxf(v.y, 0.f);
            *(float2*)(Hs + r * 260 + 2 * (tx + 32 * j)) = v;
        }
    }
    __syncthreads();

    // ================= value = V2 @ vW3 + vb3  (N=1) =======================
    float accV[4] = {0.f, 0.f, 0.f, 0.f};
    for (int k = tx; k < 256; k += 32) {
        float w = __ldg(&vW3[k]);
        #pragma unroll
        for (int i = 0; i < 4; ++i) accV[i] += Hs[(ty + 8 * i) * 260 + k] * w;
    }
    #pragma unroll
    for (int off = 16; off; off >>= 1) {
        #pragma unroll
        for (int i = 0; i < 4; ++i)
            accV[i] += __shfl_xor_sync(0xffffffffu, accV[i], off);
    }
    if (tx == 0) {
        float bb = __ldg(&vb3[0]);
        #pragma unroll
        for (int i = 0; i < 4; ++i)
            out[(size_t)NB * NOUT + m0 + ty + 8 * i] = accV[i] + bb;
    }
}

// ===========================================================================
extern "C" void kernel_launch(void* const* d_in, const int* in_sizes, int n_in,
                              void* d_out, int out_size)
{
    const float* obs = (const float*)d_in[0];
    const float* sW1 = (const float*)d_in[1];
    const float* sb1 = (const float*)d_in[2];
    const float* sW2 = (const float*)d_in[3];
    const float* sb2 = (const float*)d_in[4];
    const float* sW3 = (const float*)d_in[5];
    const float* sb3 = (const float*)d_in[6];
    const float* aW1 = (const float*)d_in[7];
    const float* ab1 = (const float*)d_in[8];
    const float* aW2 = (const float*)d_in[9];
    const float* ab2 = (const float*)d_in[10];
    const float* aW3 = (const float*)d_in[11];
    const float* ab3 = (const float*)d_in[12];
    const float* vW1 = (const float*)d_in[13];
    const float* vb1 = (const float*)d_in[14];
    const float* vW2 = (const float*)d_in[15];
    const float* vb2 = (const float*)d_in[16];
    const float* vW3 = (const float*)d_in[17];
    const float* vb3 = (const float*)d_in[18];
    float* out = (float*)d_out;

    const int smem1 = 20936 * 4;   // 83744 B
    const int smem2 = 21632 * 4;   // 86528 B
    cudaFuncSetAttribute(seq_kernel,  cudaFuncAttributeMaxDynamicSharedMemorySize, smem1);
    cudaFuncSetAttribute(head_kernel, cudaFuncAttributeMaxDynamicSharedMemorySize, smem2);

    seq_kernel<<<NB, 256, smem1>>>(obs, sW1, sb1, sW2, sb2, sW3, sb3);
    head_kernel<<<NB / 32, 256, smem2>>>(obs, aW1, ab1, aW2, ab2, aW3, ab3,
                                         vW1, vb1, vW2, vb2, vW3, vb3, out);
}

// round 6
// speedup vs baseline: 1.9106x; 1.9106x over previous
#include <cuda_runtime.h>
#include <cstdint>

// Problem constants
#define NB   16384
#define NS   37
#define NF   17
#define NOWN 9
#define NH   256
#define NE   128
#define NOUT 23
#define NTILES ((NB + 2) / 3)   // 5462 tiles of 3 batch elements

// scratch: pooled encoder output per batch row
__device__ float g_summed[(size_t)NB * NE];

// ===========================================================================
// Shared-memory layout for seq_tc (bytes from dynamic smem base)
//   A region : 32 kb-blocks x 8 mb-blocks x 512B (frag layout) = 131072
//   W1 region: 4096 8B-slots (frag layout, persistent)         =  32768 @131072
//   B region : 2 bufs x 32768                                  =  65536 @163840
//   mask     : 128 floats                                      =    512 @229376
// total 229888
// ===========================================================================
#define OFF_W1   131072u
#define OFF_B    163840u
#define OFF_MASK 229376u
#define SMEM_TC  229888

// ===========================================================================
// PTX helpers (all plain-sm_103-legal: mma.sync / cp.async / cvt.tf32)
// ===========================================================================
__device__ __forceinline__ uint32_t smem_u32(const void* p) {
    uint32_t a;
    asm("{ .reg .u64 t; cvta.to.shared.u64 t, %1; cvt.u32.u64 %0, t; }"
        : "=r"(a) : "l"(p));
    return a;
}
__device__ __forceinline__ uint32_t tf32r(float x) {
    uint32_t u; asm("cvt.rna.tf32.f32 %0, %1;" : "=r"(u) : "f"(x)); return u;
}
__device__ __forceinline__ void lds128(uint32_t r[4], uint32_t a) {
    asm volatile("ld.shared.v4.b32 {%0,%1,%2,%3}, [%4];"
                 : "=r"(r[0]), "=r"(r[1]), "=r"(r[2]), "=r"(r[3]) : "r"(a));
}
__device__ __forceinline__ void lds64(uint32_t& r0, uint32_t& r1, uint32_t a) {
    asm volatile("ld.shared.v2.b32 {%0,%1}, [%2];" : "=r"(r0), "=r"(r1) : "r"(a));
}
__device__ __forceinline__ void sts64(uint32_t a, uint32_t v0, uint32_t v1) {
    asm volatile("st.shared.v2.b32 [%0], {%1,%2};" :: "r"(a), "r"(v0), "r"(v1));
}
#define STS32(a, v) asm volatile("st.shared.b32 [%0], %1;" :: "r"(a), "r"(v) : "memory")

__device__ __forceinline__ void cpasync4(uint32_t dst, const float* g) {
    asm volatile("cp.async.ca.shared.global [%0], [%1], 4;"
                 :: "r"(dst), "l"(__cvta_generic_to_global(g)) : "memory");
}
#define CP_COMMIT() asm volatile("cp.async.commit_group;" ::: "memory")
#define CP_WAIT(n)  asm volatile("cp.async.wait_group %0;" :: "n"(n) : "memory")

// mma.sync m16n8k8 tf32: D(16x8 f32) += A(16x8 tf32) * B(8x8 tf32)
// frags (lane: g=l>>2, t=l&3):
//  a0=(g,t) a1=(g+8,t) a2=(g,t+4) a3=(g+8,t+4)
//  b0=(k=t,n=g) b1=(k=t+4,n=g)
//  c0=(g,2t) c1=(g,2t+1) c2=(g+8,2t) c3=(g+8,2t+1)
__device__ __forceinline__ void mma_tf32(float d[4], const uint32_t a[4],
                                         uint32_t b0, uint32_t b1) {
    asm volatile(
        "mma.sync.aligned.m16n8k8.row.col.f32.tf32.tf32.f32 "
        "{%0,%1,%2,%3}, {%4,%5,%6,%7}, {%8,%9}, {%0,%1,%2,%3};"
        : "+f"(d[0]), "+f"(d[1]), "+f"(d[2]), "+f"(d[3])
        : "r"(a[0]), "r"(a[1]), "r"(a[2]), "r"(a[3]), "r"(b0), "r"(b1));
}

// ---------------------------------------------------------------------------
// packed fp32x2 FMA (head_kernel)
// ---------------------------------------------------------------------------
__device__ __forceinline__ float2 ffma2(float2 a, float2 b, float2 c) {
    union U { float2 f; unsigned long long u; } A, B, C, D;
    A.f = a; B.f = b; C.f = c;
    asm("fma.rn.f32x2 %0, %1, %2, %3;" : "=l"(D.u) : "l"(A.u), "l"(B.u), "l"(C.u));
    return D.f;
}

// ===========================================================================
// seq_tc building blocks
// A frag layout: block(kb, mb) base = ((kb*8)+mb)*512; lane slot = 16B at l*16
//   holding {A[mb*16+g][kb*8+t], A[..+8][..], A[..][..+4], A[..+8][..+4]}
// B frag layout (per 32-K chunk): slot d (8B) at d*8, d = ((nt*4+kb)*32+l),
//   holding {W[k][n], W[k+4][n]} with n = nt*8 + g, k = kb*8 + t
// ===========================================================================
template<int NT>
__device__ __forceinline__ void zero_acc(float acc[][4]) {
    #pragma unroll
    for (int i = 0; i < NT; ++i) {
        acc[i][0] = 0.f; acc[i][1] = 0.f; acc[i][2] = 0.f; acc[i][3] = 0.f;
    }
}

// stage one 32-K chunk of W[K][NCOLS] (row-major) into frag layout via cp.async
template<int NCOLS>
__device__ __forceinline__ void stage_chunk(uint32_t bbuf, const float* __restrict__ Wg,
                                            int cc, int tid) {
    #pragma unroll
    for (int i = 0; i < NCOLS / 16; ++i) {
        const int d    = tid + 256 * i;
        const int lane = d & 31, kb = (d >> 5) & 3, nt = d >> 7;
        const int n    = nt * 8 + (lane >> 2);
        const int k    = cc * 32 + kb * 8 + (lane & 3);
        const float* s0 = Wg + (size_t)k * NCOLS + n;
        cpasync4(bbuf + (uint32_t)d * 8u,      s0);
        cpasync4(bbuf + (uint32_t)d * 8u + 4u, s0 + 4 * NCOLS);
    }
}

// one 32-K chunk of MMA: acc[nt] += A(chunk cc) * B(chunk buffer)
template<int NT>
__device__ __forceinline__ void mma_chunk(float acc[][4], uint32_t A_B, int cc,
                                          int w, int l, uint32_t bbuf) {
    #pragma unroll
    for (int kb = 0; kb < 4; ++kb) {
        uint32_t a[4];
        lds128(a, A_B + (uint32_t)(((cc * 4 + kb) * 8 + w) * 512 + l * 16));
        const uint32_t bbase = bbuf + (uint32_t)(kb * 256 + l * 8);
        #pragma unroll
        for (int nt = 0; nt < NT; ++nt) {
            uint32_t b0, b1;
            lds64(b0, b1, bbase + (uint32_t)(nt * 1024));
            mma_tf32(acc[nt], a, b0, b1);
        }
    }
}

// epilogue: bias + relu + tf32-round, write into A frag layout (warp-private mb=w)
template<int NT>
__device__ __forceinline__ void epi_to_A(float acc[][4], const float* __restrict__ bias,
                                         uint32_t A_B, int w, int g, int t) {
    const int c0 = 2 * t, c1 = 2 * t + 1;
    const uint32_t lo0 = (uint32_t)((4 * g + (c0 & 3)) * 16 + ((c0 & 4) ? 8 : 0));
    const uint32_t lo1 = (uint32_t)((4 * g + (c1 & 3)) * 16 + ((c1 & 4) ? 8 : 0));
    #pragma unroll
    for (int nt = 0; nt < NT; ++nt) {
        const int n0 = nt * 8 + c0;
        const float bb0 = __ldg(bias + n0), bb1 = __ldg(bias + n0 + 1);
        const uint32_t v00 = tf32r(fmaxf(acc[nt][0] + bb0, 0.f));  // (g,   c0)
        const uint32_t v10 = tf32r(fmaxf(acc[nt][2] + bb0, 0.f));  // (g+8, c0)
        const uint32_t v01 = tf32r(fmaxf(acc[nt][1] + bb1, 0.f));  // (g,   c1)
        const uint32_t v11 = tf32r(fmaxf(acc[nt][3] + bb1, 0.f));  // (g+8, c1)
        const uint32_t base = A_B + (uint32_t)((nt * 8 + w) * 512);
        sts64(base + lo0, v00, v10);
        sts64(base + lo1, v01, v11);
    }
}

// ===========================================================================
// Kernel 1: tf32 mma.sync token encoder. Persistent, 1 CTA/SM, 256 threads.
// Tile = 3 batch elements (111 token rows) padded to M=128.
// ===========================================================================
__global__ void __launch_bounds__(256, 1)
seq_tc(const float* __restrict__ obs,
       const float* __restrict__ W1, const float* __restrict__ b1,
       const float* __restrict__ W2, const float* __restrict__ b2,
       const float* __restrict__ W3, const float* __restrict__ b3)
{
    extern __shared__ float sm[];
    const int tid = threadIdx.x;
    const int w = tid >> 5, l = tid & 31;
    const int g = l >> 2, t = l & 3;
    const uint32_t sb   = smem_u32(sm);
    const uint32_t A_B  = sb;
    const uint32_t W1_B = sb + OFF_W1;
    const uint32_t B_B  = sb + OFF_B;
    float* maskS = sm + (OFF_MASK / 4);
    float* Ps    = sm + (OFF_B / 4);      // reused as 128x128 pool buffer

    // ---- persistent W1 frag staging (K padded 17->32 with zeros) ----
    for (int d = tid; d < 4096; d += 256) {
        const int lane = d & 31, kb = (d >> 5) & 3, nt = d >> 7;
        const int n = nt * 8 + (lane >> 2);
        const int k = kb * 8 + (lane & 3);
        const uint32_t v0 = (k     < NF) ? tf32r(W1[k * 256 + n])       : 0u;
        const uint32_t v1 = (k + 4 < NF) ? tf32r(W1[(k + 4) * 256 + n]) : 0u;
        sts64(W1_B + (uint32_t)d * 8u, v0, v1);
    }

    for (int tt = blockIdx.x; tt < NTILES; tt += gridDim.x) {
        const int b0 = 3 * tt;

        // ---- stage X into A frag blocks kb 0..3, compute mask ----
        if (tid < 128) {
            const int r = tid;
            float xv[32];
            #pragma unroll
            for (int c = 0; c < 32; ++c) xv[c] = 0.f;
            float s = 0.f; bool valid = false;
            if (r < 111) {
                const int j = r / 37, ss2 = r - 37 * j;
                if (b0 + j < NB) {
                    const float* xg = obs + ((size_t)(b0 + j) * 38 + 1 + ss2) * NF;
                    #pragma unroll
                    for (int c = 0; c < NF; ++c) { xv[c] = xg[c]; s += fabsf(xv[c]); }
                    valid = true;
                }
            }
            maskS[r] = (valid && s != 0.f) ? 1.f : 0.f;
            const int mb = r >> 4, rg = r & 7, rhi = (r >> 3) & 1;
            #pragma unroll
            for (int c = 0; c < 32; ++c) {
                const int kb = c >> 3, lane = 4 * rg + (c & 3);
                const int slot = (((c & 7) >> 2) << 1) + rhi;
                STS32(A_B + (uint32_t)(((kb << 3) + mb) * 512 + lane * 16 + slot * 4),
                      tf32r(xv[c]));
            }
        }
        // prefetch W2 chunk 0 while layer 1 runs
        stage_chunk<256>(B_B, W2, 0, tid);
        CP_COMMIT();
        __syncthreads();

        // ---- Layer 1: H1 = relu(X @ W1 + b1)  (K=32, B = persistent W1) ----
        float acc[32][4];
        zero_acc<32>(acc);
        mma_chunk<32>(acc, A_B, 0, w, l, W1_B);
        epi_to_A<32>(acc, b1, A_B, w, g, t);   // warp-private: no sync needed

        // ---- Layer 2: H2 = relu(H1 @ W2 + b2)  (K=256, 8 chunks) ----
        zero_acc<32>(acc);
        for (int cc = 0; cc < 8; ++cc) {
            if (cc < 7) {
                stage_chunk<256>(B_B + (uint32_t)((cc + 1) & 1) * 32768u, W2, cc + 1, tid);
                CP_COMMIT();
                CP_WAIT(1);
            } else {
                CP_WAIT(0);
            }
            __syncthreads();
            mma_chunk<32>(acc, A_B, cc, w, l, B_B + (uint32_t)(cc & 1) * 32768u);
            __syncthreads();
        }
        // prefetch W3 chunk 0 while epilogue 2 runs
        stage_chunk<128>(B_B, W3, 0, tid);
        CP_COMMIT();
        epi_to_A<32>(acc, b2, A_B, w, g, t);

        // ---- Layer 3: H3 = H2 @ W3 + b3  (K=256, N=128) ----
        float acc3[16][4];
        zero_acc<16>(acc3);
        for (int cc = 0; cc < 8; ++cc) {
            if (cc < 7) {
                stage_chunk<128>(B_B + (uint32_t)((cc + 1) & 1) * 32768u, W3, cc + 1, tid);
                CP_COMMIT();
                CP_WAIT(1);
            } else {
                CP_WAIT(0);
            }
            __syncthreads();
            mma_chunk<16>(acc3, A_B, cc, w, l, B_B + (uint32_t)(cc & 1) * 32768u);
            __syncthreads();
        }

        // ---- epilogue 3: masked relu -> Ps, then segment pooling ----
        {
            const float mk0 = maskS[16 * w + g];
            const float mk1 = maskS[16 * w + g + 8];
            const int m = 16 * w + g;
            #pragma unroll
            for (int nt = 0; nt < 16; ++nt) {
                const int n0 = nt * 8 + 2 * t;
                const float bb0 = __ldg(b3 + n0), bb1 = __ldg(b3 + n0 + 1);
                const float p00 = mk0 * fmaxf(acc3[nt][0] + bb0, 0.f);
                const float p01 = mk0 * fmaxf(acc3[nt][1] + bb1, 0.f);
                const float p10 = mk1 * fmaxf(acc3[nt][2] + bb0, 0.f);
                const float p11 = mk1 * fmaxf(acc3[nt][3] + bb1, 0.f);
                sts64(B_B + (uint32_t)((m * 128 + n0) * 4),
                      __float_as_uint(p00), __float_as_uint(p01));
                sts64(B_B + (uint32_t)(((m + 8) * 128 + n0) * 4),
                      __float_as_uint(p10), __float_as_uint(p11));
            }
        }
        __syncthreads();
        for (int idx = tid; idx < 384; idx += 256) {
            const int j = idx >> 7, c = idx & 127;
            if (b0 + j < NB) {
                float s = 0.f;
                const float* base = Ps + (size_t)(37 * j) * 128 + c;
                #pragma unroll 37
                for (int ss2 = 0; ss2 < 37; ++ss2) s += base[ss2 * 128];
                g_summed[(size_t)(b0 + j) * NE + c] = s;
            }
        }
        __syncthreads();
    }
}

// ===========================================================================
// Kernel 2: actor + value heads (unchanged FFMA2 kernel — ~220us)
// ===========================================================================
__global__ void __launch_bounds__(256, 2)
head_kernel(const float* __restrict__ obs,
            const float* __restrict__ aW1, const float* __restrict__ ab1,
            const float* __restrict__ aW2, const float* __restrict__ ab2,
            const float* __restrict__ aW3, const float* __restrict__ ab3,
            const float* __restrict__ vW1, const float* __restrict__ vb1,
            const float* __restrict__ vW2, const float* __restrict__ vb2,
            const float* __restrict__ vW3, const float* __restrict__ vb3,
            float* __restrict__ out)
{
    extern __shared__ float sm[];
    float* Cs = sm;              // 32*160 = 5120
    float* Hs = Cs + 32 * 160;   // 32*260 = 8320
    float* Ws = Hs + 32 * 260;   // 32*256 = 8192

    const int tid = threadIdx.x;
    const int tx  = tid & 31;
    const int ty  = tid >> 5;
    const int m0  = blockIdx.x * 32;

    for (int e = tid; e < 32 * 160; e += 256) {
        int r = e / 160, c = e - r * 160;
        int row = m0 + r;
        float v = 0.f;
        if (c < NE)             v = g_summed[(size_t)row * NE + c];
        else if (c < NE + NOWN) v = __ldg(&obs[(size_t)row * 38 * NF + (c - NE)]);
        Cs[e] = v;
    }

    float2 acc[4][4];

    // actor layer 1 (K=160)
    #pragma unroll
    for (int j = 0; j < 4; ++j) {
        float2 bv = __ldg(((const float2*)ab1) + tx + 32 * j);
        #pragma unroll
        for (int i = 0; i < 4; ++i) acc[i][j] = bv;
    }
    for (int cch = 0; cch < 5; ++cch) {
        __syncthreads();
        for (int i = 0; i < 32; ++i) {
            int k = cch * 32 + i;
            Ws[i * 256 + tid] = (k < NE + NOWN) ? __ldg(&aW1[k * 256 + tid]) : 0.f;
        }
        __syncthreads();
        #pragma unroll 8
        for (int kk = 0; kk < 32; ++kk) {
            float a[4];
            #pragma unroll
            for (int i = 0; i < 4; ++i) a[i] = Cs[(ty + 8 * i) * 160 + cch * 32 + kk];
            #pragma unroll
            for (int j = 0; j < 4; ++j) {
                float2 wv = *(const float2*)(Ws + kk * 256 + 2 * (tx + 32 * j));
                #pragma unroll
                for (int i = 0; i < 4; ++i)
                    acc[i][j] = ffma2(make_float2(a[i], a[i]), wv, acc[i][j]);
            }
        }
    }
    __syncthreads();
    #pragma unroll
    for (int i = 0; i < 4; ++i) {
        int r = ty + 8 * i;
        #pragma unroll
        for (int j = 0; j < 4; ++j) {
            float2 v = acc[i][j];
            v.x = fmaxf(v.x, 0.f); v.y = fmaxf(v.y, 0.f);
            *(float2*)(Hs + r * 260 + 2 * (tx + 32 * j)) = v;
        }
    }

    // actor layer 2 (K=256)
    #pragma unroll
    for (int j = 0; j < 4; ++j) {
        float2 bv = __ldg(((const float2*)ab2) + tx + 32 * j);
        #pragma unroll
        for (int i = 0; i < 4; ++i) acc[i][j] = bv;
    }
    for (int cch = 0; cch < 8; ++cch) {
        __syncthreads();
        for (int i = 0; i < 32; ++i)
            Ws[i * 256 + tid] = __ldg(&aW2[(cch * 32 + i) * 256 + tid]);
        __syncthreads();
        #pragma unroll 8
        for (int kk = 0; kk < 32; ++kk) {
            float a[4];
            #pragma unroll
            for (int i = 0; i < 4; ++i) a[i] = Hs[(ty + 8 * i) * 260 + cch * 32 + kk];
            #pragma unroll
            for (int j = 0; j < 4; ++j) {
                float2 wv = *(const float2*)(Ws + kk * 256 + 2 * (tx + 32 * j));
                #pragma unroll
                for (int i = 0; i < 4; ++i)
                    acc[i][j] = ffma2(make_float2(a[i], a[i]), wv, acc[i][j]);
            }
        }
    }
    __syncthreads();
    #pragma unroll
    for (int i = 0; i < 4; ++i) {
        int r = ty + 8 * i;
        #pragma unroll
        for (int j = 0; j < 4; ++j) {
            float2 v = acc[i][j];
            v.x = fmaxf(v.x, 0.f); v.y = fmaxf(v.y, 0.f);
            *(float2*)(Hs + r * 260 + 2 * (tx + 32 * j)) = v;
        }
    }
    __syncthreads();

    // logits
    for (int e = tid; e < 256 * NOUT; e += 256) Ws[e] = __ldg(&aW3[e]);
    __syncthreads();
    if (tx < NOUT) {
        float accL[4];
        float bb = __ldg(&ab3[tx]);
        #pragma unroll
        for (int i = 0; i < 4; ++i) accL[i] = bb;
        for (int k = 0; k < 256; ++k) {
            float wv = Ws[k * NOUT + tx];
            #pragma unroll
            for (int i = 0; i < 4; ++i) accL[i] += Hs[(ty + 8 * i) * 260 + k] * wv;
        }
        #pragma unroll
        for (int i = 0; i < 4; ++i)
            out[(size_t)(m0 + ty + 8 * i) * NOUT + tx] = accL[i];
    }

    // value layer 1 (K=160)
    #pragma unroll
    for (int j = 0; j < 4; ++j) {
        float2 bv = __ldg(((const float2*)vb1) + tx + 32 * j);
        #pragma unroll
        for (int i = 0; i < 4; ++i) acc[i][j] = bv;
    }
    for (int cch = 0; cch < 5; ++cch) {
        __syncthreads();
        for (int i = 0; i < 32; ++i) {
            int k = cch * 32 + i;
            Ws[i * 256 + tid] = (k < NE + NOWN) ? __ldg(&vW1[k * 256 + tid]) : 0.f;
        }
        __syncthreads();
        #pragma unroll 8
        for (int kk = 0; kk < 32; ++kk) {
            float a[4];
            #pragma unroll
            for (int i = 0; i < 4; ++i) a[i] = Cs[(ty + 8 * i) * 160 + cch * 32 + kk];
            #pragma unroll
            for (int j = 0; j < 4; ++j) {
                float2 wv = *(const float2*)(Ws + kk * 256 + 2 * (tx + 32 * j));
                #pragma unroll
                for (int i = 0; i < 4; ++i)
                    acc[i][j] = ffma2(make_float2(a[i], a[i]), wv, acc[i][j]);
            }
        }
    }
    __syncthreads();
    #pragma unroll
    for (int i = 0; i < 4; ++i) {
        int r = ty + 8 * i;
        #pragma unroll
        for (int j = 0; j < 4; ++j) {
            float2 v = acc[i][j];
            v.x = fmaxf(v.x, 0.f); v.y = fmaxf(v.y, 0.f);
            *(float2*)(Hs + r * 260 + 2 * (tx + 32 * j)) = v;
        }
    }

    // value layer 2 (K=256)
    #pragma unroll
    for (int j = 0; j < 4; ++j) {
        float2 bv = __ldg(((const float2*)vb2) + tx + 32 * j);
        #pragma unroll
        for (int i = 0; i < 4; ++i) acc[i][j] = bv;
    }
    for (int cch = 0; cch < 8; ++cch) {
        __syncthreads();
        for (int i = 0; i < 32; ++i)
            Ws[i * 256 + tid] = __ldg(&vW2[(cch * 32 + i) * 256 + tid]);
        __syncthreads();
        #pragma unroll 8
        for (int kk = 0; kk < 32; ++kk) {
            float a[4];
            #pragma unroll
            for (int i = 0; i < 4; ++i) a[i] = Hs[(ty + 8 * i) * 260 + cch * 32 + kk];
            #pragma unroll
            for (int j = 0; j < 4; ++j) {
                float2 wv = *(const float2*)(Ws + kk * 256 + 2 * (tx + 32 * j));
                #pragma unroll
                for (int i = 0; i < 4; ++i)
                    acc[i][j] = ffma2(make_float2(a[i], a[i]), wv, acc[i][j]);
            }
        }
    }
    __syncthreads();
    #pragma unroll
    for (int i = 0; i < 4; ++i) {
        int r = ty + 8 * i;
        #pragma unroll
        for (int j = 0; j < 4; ++j) {
            float2 v = acc[i][j];
            v.x = fmaxf(v.x, 0.f); v.y = fmaxf(v.y, 0.f);
            *(float2*)(Hs + r * 260 + 2 * (tx + 32 * j)) = v;
        }
    }
    __syncthreads();

    // value head
    float accV[4] = {0.f, 0.f, 0.f, 0.f};
    for (int k = tx; k < 256; k += 32) {
        float wv = __ldg(&vW3[k]);
        #pragma unroll
        for (int i = 0; i < 4; ++i) accV[i] += Hs[(ty + 8 * i) * 260 + k] * wv;
    }
    #pragma unroll
    for (int off = 16; off; off >>= 1) {
        #pragma unroll
        for (int i = 0; i < 4; ++i)
            accV[i] += __shfl_xor_sync(0xffffffffu, accV[i], off);
    }
    if (tx == 0) {
        float bb = __ldg(&vb3[0]);
        #pragma unroll
        for (int i = 0; i < 4; ++i)
            out[(size_t)NB * NOUT + m0 + ty + 8 * i] = accV[i] + bb;
    }
}

// ===========================================================================
extern "C" void kernel_launch(void* const* d_in, const int* in_sizes, int n_in,
                              void* d_out, int out_size)
{
    const float* obs = (const float*)d_in[0];
    const float* sW1 = (const float*)d_in[1];
    const float* sb1 = (const float*)d_in[2];
    const float* sW2 = (const float*)d_in[3];
    const float* sb2 = (const float*)d_in[4];
    const float* sW3 = (const float*)d_in[5];
    const float* sb3 = (const float*)d_in[6];
    const float* aW1 = (const float*)d_in[7];
    const float* ab1 = (const float*)d_in[8];
    const float* aW2 = (const float*)d_in[9];
    const float* ab2 = (const float*)d_in[10];
    const float* aW3 = (const float*)d_in[11];
    const float* ab3 = (const float*)d_in[12];
    const float* vW1 = (const float*)d_in[13];
    const float* vb1 = (const float*)d_in[14];
    const float* vW2 = (const float*)d_in[15];
    const float* vb2 = (const float*)d_in[16];
    const float* vW3 = (const float*)d_in[17];
    const float* vb3 = (const float*)d_in[18];
    float* out = (float*)d_out;

    const int smem2 = 21632 * 4;
    cudaFuncSetAttribute(seq_tc,      cudaFuncAttributeMaxDynamicSharedMemorySize, SMEM_TC);
    cudaFuncSetAttribute(head_kernel, cudaFuncAttributeMaxDynamicSharedMemorySize, smem2);

    seq_tc<<<152, 256, SMEM_TC>>>(obs, sW1, sb1, sW2, sb2, sW3, sb3);
    head_kernel<<<NB / 32, 256, smem2>>>(obs, aW1, ab1, aW2, ab2, aW3, ab3,
                                         vW1, vb1, vW2, vb2, vW3, vb3, out);
}

// round 8
// speedup vs baseline: 2.9325x; 1.5349x over previous
#include <cuda_runtime.h>
#include <cstdint>

// Problem constants
#define NB   16384
#define NS   37
#define NF   17
#define NOWN 9
#define NH   256
#define NE   128
#define NOUT 23
#define NTILES ((NB + 2) / 3)   // 5462 tiles of 3 batch elements

// scratch: pooled encoder output per batch row
__device__ float g_summed[(size_t)NB * NE];
// pre-rounded (RNA tf32) encoder weights
__device__ float g_W1r[NF * NH];        // 17*256
__device__ float g_W2r[NH * NH];        // 256*256
__device__ float g_W3r[NH * NE];        // 256*128

// ===========================================================================
// Shared-memory layout for seq_tc (bytes from dynamic smem base)
//   A region : 32 kb-blocks x 8 mb-blocks x 512B (frag layout) = 131072 @0
//   W1 region: 24 k-rows x 1056B (row-major, padded pitch)     =  25344 @131072
//   B region : 2 bufs x 32 k-rows x 1056B                      =  67584 @156416
//   mask     : 128 floats                                      =    512 @224000
// total 224512   (Ps pool buffer [128 x 132 f32] reuses the B region)
// ===========================================================================
#define OFF_W1   131072u
#define OFF_B    156416u
#define OFF_MASK 224000u
#define SMEM_TC  224512
#define BPITCH   1056u
#define BBUF_SZ  33792u

// ===========================================================================
// PTX helpers (plain-sm_103-legal: mma.sync / cp.async / cvt.tf32)
// ===========================================================================
__device__ __forceinline__ uint32_t smem_u32(const void* p) {
    uint32_t a;
    asm("{ .reg .u64 t; cvta.to.shared.u64 t, %1; cvt.u32.u64 %0, t; }"
        : "=r"(a) : "l"(p));
    return a;
}
__device__ __forceinline__ uint32_t tf32r(float x) {
    uint32_t u; asm("cvt.rna.tf32.f32 %0, %1;" : "=r"(u) : "f"(x)); return u;
}
__device__ __forceinline__ void lds128(uint32_t r[4], uint32_t a) {
    asm volatile("ld.shared.v4.b32 {%0,%1,%2,%3}, [%4];"
                 : "=r"(r[0]), "=r"(r[1]), "=r"(r[2]), "=r"(r[3]) : "r"(a));
}
__device__ __forceinline__ uint32_t lds32(uint32_t a) {
    uint32_t v; asm volatile("ld.shared.b32 %0, [%1];" : "=r"(v) : "r"(a)); return v;
}
__device__ __forceinline__ void sts64(uint32_t a, uint32_t v0, uint32_t v1) {
    asm volatile("st.shared.v2.b32 [%0], {%1,%2};" :: "r"(a), "r"(v0), "r"(v1));
}
#define STS32(a, v) asm volatile("st.shared.b32 [%0], %1;" :: "r"(a), "r"(v) : "memory")

__device__ __forceinline__ void cpasync16(uint32_t dst, const float* g) {
    asm volatile("cp.async.cg.shared.global [%0], [%1], 16;"
                 :: "r"(dst), "l"(__cvta_generic_to_global(g)) : "memory");
}
#define CP_COMMIT() asm volatile("cp.async.commit_group;" ::: "memory")
#define CP_WAIT(n)  asm volatile("cp.async.wait_group %0;" :: "n"(n) : "memory")

// mma.sync m16n8k8 tf32 frags (lane: g=l>>2, t=l&3):
//  a0=(g,t) a1=(g+8,t) a2=(g,t+4) a3=(g+8,t+4)
//  b0=(k=t,n=g) b1=(k=t+4,n=g)
//  c0=(g,2t) c1=(g,2t+1) c2=(g+8,2t) c3=(g+8,2t+1)
__device__ __forceinline__ void mma_tf32(float d[4], const uint32_t a[4],
                                         uint32_t b0, uint32_t b1) {
    asm volatile(
        "mma.sync.aligned.m16n8k8.row.col.f32.tf32.tf32.f32 "
        "{%0,%1,%2,%3}, {%4,%5,%6,%7}, {%8,%9}, {%0,%1,%2,%3};"
        : "+f"(d[0]), "+f"(d[1]), "+f"(d[2]), "+f"(d[3])
        : "r"(a[0]), "r"(a[1]), "r"(a[2]), "r"(a[3]), "r"(b0), "r"(b1));
}

// ---------------------------------------------------------------------------
// packed fp32x2 FMA (head_kernel)
// ---------------------------------------------------------------------------
__device__ __forceinline__ float2 ffma2(float2 a, float2 b, float2 c) {
    union U { float2 f; unsigned long long u; } A, B, C, D;
    A.f = a; B.f = b; C.f = c;
    asm("fma.rn.f32x2 %0, %1, %2, %3;" : "=l"(D.u) : "l"(A.u), "l"(B.u), "l"(C.u));
    return D.f;
}

// ===========================================================================
// Kernel 0: RNA-round encoder weights into device scratch (runs every launch,
// deterministic; ~100K elements, ~5us)
// ===========================================================================
__global__ void round_weights(const float* __restrict__ W1,
                              const float* __restrict__ W2,
                              const float* __restrict__ W3)
{
    const int stride = gridDim.x * blockDim.x;
    for (int i = blockIdx.x * blockDim.x + threadIdx.x; i < NF * NH; i += stride)
        g_W1r[i] = __uint_as_float(tf32r(W1[i]));
    for (int i = blockIdx.x * blockDim.x + threadIdx.x; i < NH * NH; i += stride)
        g_W2r[i] = __uint_as_float(tf32r(W2[i]));
    for (int i = blockIdx.x * blockDim.x + threadIdx.x; i < NH * NE; i += stride)
        g_W3r[i] = __uint_as_float(tf32r(W3[i]));
}

// ===========================================================================
// seq_tc building blocks
// A frag layout: block (kbG, mb) base = (kbG*8 + mb)*512; lane slot 16B at l*16
//   words: {A[mb*16+g][kb*8+t], A[..+8][..], A[..][..+4], A[..+8][..+4]}
// B smem layout: row-major [32 k x NCOLS n], pitch BPITCH bytes per k-row.
//   frag fetch b0 = B[kb*8+t][n], b1 = B[kb*8+t+4][n]; pitch 1056 makes the
//   lane bank = (8t + 8nt + g) mod 32  -> conflict-free.
// ===========================================================================

// stage one 32-K chunk of W[K][NCOLS] (row-major fp32) via 16B cp.async
template<int NCOLS>
__device__ __forceinline__ void stage16(uint32_t bbuf, const float* __restrict__ Wg,
                                        int cc, int tid) {
    constexpr int CPR = NCOLS / 4;       // 16B chunks per k-row
    constexpr int TOT = 32 * CPR;
    #pragma unroll
    for (int i = 0; i < TOT / 256; ++i) {
        const int d  = tid + 256 * i;
        const int kr = d / CPR;
        const int cf = (d % CPR) * 4;    // float offset in row
        cpasync16(bbuf + (uint32_t)kr * BPITCH + (uint32_t)cf * 4u,
                  Wg + (size_t)(cc * 32 + kr) * NCOLS + cf);
    }
}

// one kb (K=8) step: acc[mbl][ntl] += A(kbG, 4wy+mbl) * B rows (kb*8+t, +4)
template<int NTW>
__device__ __forceinline__ void mma_kb(float (&acc)[4][NTW][4], uint32_t A_B,
                                       int kbG, int wy, uint32_t bbuf, int kb,
                                       int ntbase, int l, int g, int t) {
    uint32_t a[4][4];
    #pragma unroll
    for (int mbl = 0; mbl < 4; ++mbl)
        lds128(a[mbl], A_B + (uint32_t)((kbG * 8 + 4 * wy + mbl) * 512 + l * 16));
    const uint32_t b0row = bbuf + (uint32_t)(kb * 8 + t) * BPITCH;
    #pragma unroll
    for (int ntl = 0; ntl < NTW; ++ntl) {
        const uint32_t noff = (uint32_t)(((ntbase + ntl) * 8 + g) * 4);
        const uint32_t b0 = lds32(b0row + noff);
        const uint32_t b1 = lds32(b0row + 4u * BPITCH + noff);
        #pragma unroll
        for (int mbl = 0; mbl < 4; ++mbl)
            mma_tf32(acc[mbl][ntl], a[mbl], b0, b1);
    }
}

template<int NTW>
__device__ __forceinline__ void zacc(float (&acc)[4][NTW][4]) {
    #pragma unroll
    for (int i = 0; i < 4; ++i)
        #pragma unroll
        for (int j = 0; j < NTW; ++j) {
            acc[i][j][0] = 0.f; acc[i][j][1] = 0.f;
            acc[i][j][2] = 0.f; acc[i][j][3] = 0.f;
        }
}

// epilogue: bias + relu + tf32-round, write back into A frag layout
template<int NTW>
__device__ __forceinline__ void epi2A(float (&acc)[4][NTW][4],
                                      const float* __restrict__ bias,
                                      uint32_t A_B, int wy, int ntbase,
                                      int g, int t) {
    const int c0 = 2 * t, c1 = 2 * t + 1;
    const uint32_t lo0 = (uint32_t)((4 * g + (c0 & 3)) * 16 + ((c0 & 4) ? 8 : 0));
    const uint32_t lo1 = (uint32_t)((4 * g + (c1 & 3)) * 16 + ((c1 & 4) ? 8 : 0));
    #pragma unroll
    for (int ntl = 0; ntl < NTW; ++ntl) {
        const int ntG = ntbase + ntl;
        const int n0  = ntG * 8 + c0;
        const float bb0 = __ldg(bias + n0), bb1 = __ldg(bias + n0 + 1);
        #pragma unroll
        for (int mbl = 0; mbl < 4; ++mbl) {
            const uint32_t base = A_B + (uint32_t)((ntG * 8 + 4 * wy + mbl) * 512);
            sts64(base + lo0, tf32r(fmaxf(acc[mbl][ntl][0] + bb0, 0.f)),
                              tf32r(fmaxf(acc[mbl][ntl][2] + bb0, 0.f)));
            sts64(base + lo1, tf32r(fmaxf(acc[mbl][ntl][1] + bb1, 0.f)),
                              tf32r(fmaxf(acc[mbl][ntl][3] + bb1, 0.f)));
        }
    }
}

// ===========================================================================
// Kernel 1: tf32 mma.sync token encoder. Persistent, 1 CTA/SM, 256 threads.
// Tile = 3 batch elements (111 token rows) padded to M=128.
// Warp (wy = w>>2, wx = w&3): rows [64wy, 64wy+64), cols quarter wx.
// ===========================================================================
__global__ void __launch_bounds__(256, 1)
seq_tc(const float* __restrict__ obs,
       const float* __restrict__ b1,
       const float* __restrict__ b2,
       const float* __restrict__ b3)
{
    extern __shared__ float sm[];
    const int tid = threadIdx.x;
    const int w = tid >> 5, l = tid & 31;
    const int g = l >> 2, t = l & 3;
    const int wy = w >> 2, wx = w & 3;
    const uint32_t sb   = smem_u32(sm);
    const uint32_t A_B  = sb;
    const uint32_t W1_B = sb + OFF_W1;
    const uint32_t B_B  = sb + OFF_B;
    float* maskS = sm + (OFF_MASK / 4);
    float* Ps    = sm + (OFF_B / 4);      // 128 x 132 pool buffer (reuses B bufs)

    // ---- persistent W1 staging (pre-rounded): rows 0..16 cp.async, 17..23 zero
    for (int d = tid; d < 1088; d += 256) {           // 17 rows x 64 chunks
        const int kr = d >> 6, cf = (d & 63) * 4;
        cpasync16(W1_B + (uint32_t)kr * BPITCH + (uint32_t)cf * 4u,
                  g_W1r + (size_t)kr * 256 + cf);
    }
    CP_COMMIT();
    for (int d = tid; d < 1848; d += 256)             // 7 rows x 264 words
        STS32(W1_B + 17u * BPITCH + (uint32_t)d * 4u, 0u);
    CP_WAIT(0);
    __syncthreads();

    for (int tt = blockIdx.x; tt < NTILES; tt += gridDim.x) {
        const int b0 = 3 * tt;

        // ---- stage X into A frag blocks kb 0..2 (K=24), compute mask ----
        if (tid < 128) {
            const int r = tid;
            float xv[24];
            #pragma unroll
            for (int c = 0; c < 24; ++c) xv[c] = 0.f;
            float s = 0.f; bool valid = false;
            if (r < 111) {
                const int j = r / 37, ss2 = r - 37 * j;
                if (b0 + j < NB) {
                    const float* xg = obs + ((size_t)(b0 + j) * 38 + 1 + ss2) * NF;
                    #pragma unroll
                    for (int c = 0; c < NF; ++c) { xv[c] = xg[c]; s += fabsf(xv[c]); }
                    valid = true;
                }
            }
            maskS[r] = (valid && s != 0.f) ? 1.f : 0.f;
            const int mb = r >> 4, rg = r & 7, rhi = (r >> 3) & 1;
            #pragma unroll
            for (int c = 0; c < 24; ++c) {
                const int kb = c >> 3, lane = 4 * rg + (c & 3);
                const int slot = (((c & 7) >> 2) << 1) + rhi;
                STS32(A_B + (uint32_t)((kb * 8 + mb) * 512 + lane * 16 + slot * 4),
                      tf32r(xv[c]));
            }
        }
        // prefetch W2 chunk 0 while layer 1 runs
        stage16<256>(B_B, g_W2r, 0, tid);
        CP_COMMIT();
        __syncthreads();

        // ---- Layer 1: H1 = relu(X @ W1 + b1)  (K=24) ----
        float acc[4][8][4];
        zacc<8>(acc);
        #pragma unroll
        for (int kb = 0; kb < 3; ++kb)
            mma_kb<8>(acc, A_B, kb, wy, W1_B, kb, 8 * wx, l, g, t);
        __syncthreads();                         // all X reads done
        epi2A<8>(acc, b1, A_B, wy, 8 * wx, g, t);
        __syncthreads();

        // ---- Layer 2: H2 = relu(H1 @ W2 + b2)  (K=256, 8 chunks) ----
        zacc<8>(acc);
        for (int cc = 0; cc < 8; ++cc) {
            if (cc < 7) {
                stage16<256>(B_B + (uint32_t)((cc + 1) & 1) * BBUF_SZ, g_W2r, cc + 1, tid);
                CP_COMMIT();
                CP_WAIT(1);
            } else {
                CP_WAIT(0);
            }
            __syncthreads();
            const uint32_t bb = B_B + (uint32_t)(cc & 1) * BBUF_SZ;
            #pragma unroll
            for (int kb = 0; kb < 4; ++kb)
                mma_kb<8>(acc, A_B, cc * 4 + kb, wy, bb, kb, 8 * wx, l, g, t);
            __syncthreads();
        }
        // prefetch W3 chunk 0 while epilogue 2 runs
        stage16<128>(B_B, g_W3r, 0, tid);
        CP_COMMIT();
        epi2A<8>(acc, b2, A_B, wy, 8 * wx, g, t);
        __syncthreads();

        // ---- Layer 3: H3 = H2 @ W3 + b3  (K=256, N=128) ----
        float acc3[4][4][4];
        zacc<4>(acc3);
        for (int cc = 0; cc < 8; ++cc) {
            if (cc < 7) {
                stage16<128>(B_B + (uint32_t)((cc + 1) & 1) * BBUF_SZ, g_W3r, cc + 1, tid);
                CP_COMMIT();
                CP_WAIT(1);
            } else {
                CP_WAIT(0);
            }
            __syncthreads();
            const uint32_t bb = B_B + (uint32_t)(cc & 1) * BBUF_SZ;
            #pragma unroll
            for (int kb = 0; kb < 4; ++kb)
                mma_kb<4>(acc3, A_B, cc * 4 + kb, wy, bb, kb, 4 * wx, l, g, t);
            __syncthreads();
        }

        // ---- epilogue 3: masked relu -> Ps (stride 132), segment pooling ----
        #pragma unroll
        for (int mbl = 0; mbl < 4; ++mbl) {
            const int m = 64 * wy + 16 * mbl + g;
            const float mk0 = maskS[m], mk1 = maskS[m + 8];
            #pragma unroll
            for (int ntl = 0; ntl < 4; ++ntl) {
                const int n0 = (4 * wx + ntl) * 8 + 2 * t;
                const float bb0 = __ldg(b3 + n0), bb1 = __ldg(b3 + n0 + 1);
                const float p00 = mk0 * fmaxf(acc3[mbl][ntl][0] + bb0, 0.f);
                const float p01 = mk0 * fmaxf(acc3[mbl][ntl][1] + bb1, 0.f);
                const float p10 = mk1 * fmaxf(acc3[mbl][ntl][2] + bb0, 0.f);
                const float p11 = mk1 * fmaxf(acc3[mbl][ntl][3] + bb1, 0.f);
                sts64(B_B + (uint32_t)((m * 132 + n0) * 4),
                      __float_as_uint(p00), __float_as_uint(p01));
                sts64(B_B + (uint32_t)(((m + 8) * 132 + n0) * 4),
                      __float_as_uint(p10), __float_as_uint(p11));
            }
        }
        __syncthreads();
        for (int idx = tid; idx < 384; idx += 256) {
            const int j = idx >> 7, c = idx & 127;
            if (b0 + j < NB) {
                float s = 0.f;
                const float* base = Ps + (size_t)(37 * j) * 132 + c;
                #pragma unroll 37
                for (int ss2 = 0; ss2 < 37; ++ss2) s += base[ss2 * 132];
                g_summed[(size_t)(b0 + j) * NE + c] = s;
            }
        }
        __syncthreads();
    }
}

// ===========================================================================
// Kernel 2: actor + value heads (unchanged FFMA2 kernel — ~220us)
// ===========================================================================
__global__ void __launch_bounds__(256, 2)
head_kernel(const float* __restrict__ obs,
            const float* __restrict__ aW1, const float* __restrict__ ab1,
            const float* __restrict__ aW2, const float* __restrict__ ab2,
            const float* __restrict__ aW3, const float* __restrict__ ab3,
            const float* __restrict__ vW1, const float* __restrict__ vb1,
            const float* __restrict__ vW2, const float* __restrict__ vb2,
            const float* __restrict__ vW3, const float* __restrict__ vb3,
            float* __restrict__ out)
{
    extern __shared__ float sm[];
    float* Cs = sm;              // 32*160 = 5120
    float* Hs = Cs + 32 * 160;   // 32*260 = 8320
    float* Ws = Hs + 32 * 260;   // 32*256 = 8192

    const int tid = threadIdx.x;
    const int tx  = tid & 31;
    const int ty  = tid >> 5;
    const int m0  = blockIdx.x * 32;

    for (int e = tid; e < 32 * 160; e += 256) {
        int r = e / 160, c = e - r * 160;
        int row = m0 + r;
        float v = 0.f;
        if (c < NE)             v = g_summed[(size_t)row * NE + c];
        else if (c < NE + NOWN) v = __ldg(&obs[(size_t)row * 38 * NF + (c - NE)]);
        Cs[e] = v;
    }

    float2 acc[4][4];

    // actor layer 1 (K=160)
    #pragma unroll
    for (int j = 0; j < 4; ++j) {
        float2 bv = __ldg(((const float2*)ab1) + tx + 32 * j);
        #pragma unroll
        for (int i = 0; i < 4; ++i) acc[i][j] = bv;
    }
    for (int cch = 0; cch < 5; ++cch) {
        __syncthreads();
        for (int i = 0; i < 32; ++i) {
            int k = cch * 32 + i;
            Ws[i * 256 + tid] = (k < NE + NOWN) ? __ldg(&aW1[k * 256 + tid]) : 0.f;
        }
        __syncthreads();
        #pragma unroll 8
        for (int kk = 0; kk < 32; ++kk) {
            float a[4];
            #pragma unroll
            for (int i = 0; i < 4; ++i) a[i] = Cs[(ty + 8 * i) * 160 + cch * 32 + kk];
            #pragma unroll
            for (int j = 0; j < 4; ++j) {
                float2 wv = *(const float2*)(Ws + kk * 256 + 2 * (tx + 32 * j));
                #pragma unroll
                for (int i = 0; i < 4; ++i)
                    acc[i][j] = ffma2(make_float2(a[i], a[i]), wv, acc[i][j]);
            }
        }
    }
    __syncthreads();
    #pragma unroll
    for (int i = 0; i < 4; ++i) {
        int r = ty + 8 * i;
        #pragma unroll
        for (int j = 0; j < 4; ++j) {
            float2 v = acc[i][j];
            v.x = fmaxf(v.x, 0.f); v.y = fmaxf(v.y, 0.f);
            *(float2*)(Hs + r * 260 + 2 * (tx + 32 * j)) = v;
        }
    }

    // actor layer 2 (K=256)
    #pragma unroll
    for (int j = 0; j < 4; ++j) {
        float2 bv = __ldg(((const float2*)ab2) + tx + 32 * j);
        #pragma unroll
        for (int i = 0; i < 4; ++i) acc[i][j] = bv;
    }
    for (int cch = 0; cch < 8; ++cch) {
        __syncthreads();
        for (int i = 0; i < 32; ++i)
            Ws[i * 256 + tid] = __ldg(&aW2[(cch * 32 + i) * 256 + tid]);
        __syncthreads();
        #pragma unroll 8
        for (int kk = 0; kk < 32; ++kk) {
            float a[4];
            #pragma unroll
            for (int i = 0; i < 4; ++i) a[i] = Hs[(ty + 8 * i) * 260 + cch * 32 + kk];
            #pragma unroll
            for (int j = 0; j < 4; ++j) {
                float2 wv = *(const float2*)(Ws + kk * 256 + 2 * (tx + 32 * j));
                #pragma unroll
                for (int i = 0; i < 4; ++i)
                    acc[i][j] = ffma2(make_float2(a[i], a[i]), wv, acc[i][j]);
            }
        }
    }
    __syncthreads();
    #pragma unroll
    for (int i = 0; i < 4; ++i) {
        int r = ty + 8 * i;
        #pragma unroll
        for (int j = 0; j < 4; ++j) {
            float2 v = acc[i][j];
            v.x = fmaxf(v.x, 0.f); v.y = fmaxf(v.y, 0.f);
            *(float2*)(Hs + r * 260 + 2 * (tx + 32 * j)) = v;
        }
    }
    __syncthreads();

    // logits
    for (int e = tid; e < 256 * NOUT; e += 256) Ws[e] = __ldg(&aW3[e]);
    __syncthreads();
    if (tx < NOUT) {
        float accL[4];
        float bb = __ldg(&ab3[tx]);
        #pragma unroll
        for (int i = 0; i < 4; ++i) accL[i] = bb;
        for (int k = 0; k < 256; ++k) {
            float wv = Ws[k * NOUT + tx];
            #pragma unroll
            for (int i = 0; i < 4; ++i) accL[i] += Hs[(ty + 8 * i) * 260 + k] * wv;
        }
        #pragma unroll
        for (int i = 0; i < 4; ++i)
            out[(size_t)(m0 + ty + 8 * i) * NOUT + tx] = accL[i];
    }

    // value layer 1 (K=160)
    #pragma unroll
    for (int j = 0; j < 4; ++j) {
        float2 bv = __ldg(((const float2*)vb1) + tx + 32 * j);
        #pragma unroll
        for (int i = 0; i < 4; ++i) acc[i][j] = bv;
    }
    for (int cch = 0; cch < 5; ++cch) {
        __syncthreads();
        for (int i = 0; i < 32; ++i) {
            int k = cch * 32 + i;
            Ws[i * 256 + tid] = (k < NE + NOWN) ? __ldg(&vW1[k * 256 + tid]) : 0.f;
        }
        __syncthreads();
        #pragma unroll 8
        for (int kk = 0; kk < 32; ++kk) {
            float a[4];
            #pragma unroll
            for (int i = 0; i < 4; ++i) a[i] = Cs[(ty + 8 * i) * 160 + cch * 32 + kk];
            #pragma unroll
            for (int j = 0; j < 4; ++j) {
                float2 wv = *(const float2*)(Ws + kk * 256 + 2 * (tx + 32 * j));
                #pragma unroll
                for (int i = 0; i < 4; ++i)
                    acc[i][j] = ffma2(make_float2(a[i], a[i]), wv, acc[i][j]);
            }
        }
    }
    __syncthreads();
    #pragma unroll
    for (int i = 0; i < 4; ++i) {
        int r = ty + 8 * i;
        #pragma unroll
        for (int j = 0; j < 4; ++j) {
            float2 v = acc[i][j];
            v.x = fmaxf(v.x, 0.f); v.y = fmaxf(v.y, 0.f);
            *(float2*)(Hs + r * 260 + 2 * (tx + 32 * j)) = v;
        }
    }

    // value layer 2 (K=256)
    #pragma unroll
    for (int j = 0; j < 4; ++j) {
        float2 bv = __ldg(((const float2*)vb2) + tx + 32 * j);
        #pragma unroll
        for (int i = 0; i < 4; ++i) acc[i][j] = bv;
    }
    for (int cch = 0; cch < 8; ++cch) {
        __syncthreads();
        for (int i = 0; i < 32; ++i)
            Ws[i * 256 + tid] = __ldg(&vW2[(cch * 32 + i) * 256 + tid]);
        __syncthreads();
        #pragma unroll 8
        for (int kk = 0; kk < 32; ++kk) {
            float a[4];
            #pragma unroll
            for (int i = 0; i < 4; ++i) a[i] = Hs[(ty + 8 * i) * 260 + cch * 32 + kk];
            #pragma unroll
            for (int j = 0; j < 4; ++j) {
                float2 wv = *(const float2*)(Ws + kk * 256 + 2 * (tx + 32 * j));
                #pragma unroll
                for (int i = 0; i < 4; ++i)
                    acc[i][j] = ffma2(make_float2(a[i], a[i]), wv, acc[i][j]);
            }
        }
    }
    __syncthreads();
    #pragma unroll
    for (int i = 0; i < 4; ++i) {
        int r = ty + 8 * i;
        #pragma unroll
        for (int j = 0; j < 4; ++j) {
            float2 v = acc[i][j];
            v.x = fmaxf(v.x, 0.f); v.y = fmaxf(v.y, 0.f);
            *(float2*)(Hs + r * 260 + 2 * (tx + 32 * j)) = v;
        }
    }
    __syncthreads();

    // value head
    float accV[4] = {0.f, 0.f, 0.f, 0.f};
    for (int k = tx; k < 256; k += 32) {
        float wv = __ldg(&vW3[k]);
        #pragma unroll
        for (int i = 0; i < 4; ++i) accV[i] += Hs[(ty + 8 * i) * 260 + k] * wv;
    }
    #pragma unroll
    for (int off = 16; off; off >>= 1) {
        #pragma unroll
        for (int i = 0; i < 4; ++i)
            accV[i] += __shfl_xor_sync(0xffffffffu, accV[i], off);
    }
    if (tx == 0) {
        float bb = __ldg(&vb3[0]);
        #pragma unroll
        for (int i = 0; i < 4; ++i)
            out[(size_t)NB * NOUT + m0 + ty + 8 * i] = accV[i] + bb;
    }
}

// ===========================================================================
extern "C" void kernel_launch(void* const* d_in, const int* in_sizes, int n_in,
                              void* d_out, int out_size)
{
    const float* obs = (const float*)d_in[0];
    const float* sW1 = (const float*)d_in[1];
    const float* sb1 = (const float*)d_in[2];
    const float* sW2 = (const float*)d_in[3];
    const float* sb2 = (const float*)d_in[4];
    const float* sW3 = (const float*)d_in[5];
    const float* sb3 = (const float*)d_in[6];
    const float* aW1 = (const float*)d_in[7];
    const float* ab1 = (const float*)d_in[8];
    const float* aW2 = (const float*)d_in[9];
    const float* ab2 = (const float*)d_in[10];
    const float* aW3 = (const float*)d_in[11];
    const float* ab3 = (const float*)d_in[12];
    const float* vW1 = (const float*)d_in[13];
    const float* vb1 = (const float*)d_in[14];
    const float* vW2 = (const float*)d_in[15];
    const float* vb2 = (const float*)d_in[16];
    const float* vW3 = (const float*)d_in[17];
    const float* vb3 = (const float*)d_in[18];
    float* out = (float*)d_out;

    const int smem2 = 21632 * 4;
    cudaFuncSetAttribute(seq_tc,      cudaFuncAttributeMaxDynamicSharedMemorySize, SMEM_TC);
    cudaFuncSetAttribute(head_kernel, cudaFuncAttributeMaxDynamicSharedMemorySize, smem2);

    round_weights<<<128, 256>>>(sW1, sW2, sW3);
    seq_tc<<<152, 256, SMEM_TC>>>(obs, sb1, sb2, sb3);
    head_kernel<<<NB / 32, 256, smem2>>>(obs, aW1, ab1, aW2, ab2, aW3, ab3,
                                         vW1, vb1, vW2, vb2, vW3, vb3, out);
}

// round 9
// speedup vs baseline: 3.3325x; 1.1364x over previous
#include <cuda_runtime.h>
#include <cstdint>

// Problem constants
#define NB   16384
#define NS   37
#define NF   17
#define NOWN 9
#define NH   256
#define NE   128
#define NOUT 23
#define NTILES ((NB + 2) / 3)   // 5462 tiles of 3 batch elements

// scratch: pooled encoder output per batch row
__device__ float g_summed[(size_t)NB * NE];
// pre-rounded (RNA tf32) encoder weights
__device__ float g_W1r[NF * NH];        // 17*256
__device__ float g_W2r[NH * NH];        // 256*256
__device__ float g_W3r[NH * NE];        // 256*128
// pre-rounded + K-padded head weights (rows >= 137 zero)
__device__ float g_aW1p[160 * NH];
__device__ float g_vW1p[160 * NH];
__device__ float g_aW2r[NH * NH];
__device__ float g_vW2r[NH * NH];

// ===========================================================================
// Shared-memory layout for seq_tc (bytes from dynamic smem base)
// ===========================================================================
#define OFF_W1   131072u
#define OFF_B    156416u
#define OFF_MASK 224000u
#define SMEM_TC  224512
#define BPITCH   1056u
#define BBUF_SZ  33792u

// head_tc smem layout:
//   cat frag : 20 kb x 4 mb x 512  = 40960 @ 0
//   H frag   : 32 kb x 4 mb x 512  = 65536 @ 40960   (also aW3 plain staging)
//   B region : 2 x 33792 = 67584   @ 106496          (also H2 plain [64 x 260])
#define HOFF_H   40960u
#define HOFF_B   106496u
#define SMEM_HD  174080

// ===========================================================================
// PTX helpers (plain-sm_103-legal: mma.sync / cp.async / cvt.tf32)
// ===========================================================================
__device__ __forceinline__ uint32_t smem_u32(const void* p) {
    uint32_t a;
    asm("{ .reg .u64 t; cvta.to.shared.u64 t, %1; cvt.u32.u64 %0, t; }"
        : "=r"(a) : "l"(p));
    return a;
}
__device__ __forceinline__ uint32_t tf32r(float x) {
    uint32_t u; asm("cvt.rna.tf32.f32 %0, %1;" : "=r"(u) : "f"(x)); return u;
}
__device__ __forceinline__ void lds128(uint32_t r[4], uint32_t a) {
    asm volatile("ld.shared.v4.b32 {%0,%1,%2,%3}, [%4];"
                 : "=r"(r[0]), "=r"(r[1]), "=r"(r[2]), "=r"(r[3]) : "r"(a));
}
__device__ __forceinline__ uint32_t lds32(uint32_t a) {
    uint32_t v; asm volatile("ld.shared.b32 %0, [%1];" : "=r"(v) : "r"(a)); return v;
}
__device__ __forceinline__ void sts64(uint32_t a, uint32_t v0, uint32_t v1) {
    asm volatile("st.shared.v2.b32 [%0], {%1,%2};" :: "r"(a), "r"(v0), "r"(v1));
}
#define STS32(a, v) asm volatile("st.shared.b32 [%0], %1;" :: "r"(a), "r"(v) : "memory")

__device__ __forceinline__ void cpasync16(uint32_t dst, const float* g) {
    asm volatile("cp.async.cg.shared.global [%0], [%1], 16;"
                 :: "r"(dst), "l"(__cvta_generic_to_global(g)) : "memory");
}
#define CP_COMMIT() asm volatile("cp.async.commit_group;" ::: "memory")
#define CP_WAIT(n)  asm volatile("cp.async.wait_group %0;" :: "n"(n) : "memory")

// mma.sync m16n8k8 tf32 frags (lane: g=l>>2, t=l&3):
//  a0=(g,t) a1=(g+8,t) a2=(g,t+4) a3=(g+8,t+4)
//  b0=(k=t,n=g) b1=(k=t+4,n=g)
//  c0=(g,2t) c1=(g,2t+1) c2=(g+8,2t) c3=(g+8,2t+1)
__device__ __forceinline__ void mma_tf32(float d[4], const uint32_t a[4],
                                         uint32_t b0, uint32_t b1) {
    asm volatile(
        "mma.sync.aligned.m16n8k8.row.col.f32.tf32.tf32.f32 "
        "{%0,%1,%2,%3}, {%4,%5,%6,%7}, {%8,%9}, {%0,%1,%2,%3};"
        : "+f"(d[0]), "+f"(d[1]), "+f"(d[2]), "+f"(d[3])
        : "r"(a[0]), "r"(a[1]), "r"(a[2]), "r"(a[3]), "r"(b0), "r"(b1));
}

// ===========================================================================
// Kernel 0: RNA-round (+pad) all MMA weights into device scratch (~10us)
// ===========================================================================
__global__ void round_weights(const float* __restrict__ W1,
                              const float* __restrict__ W2,
                              const float* __restrict__ W3,
                              const float* __restrict__ aW1,
                              const float* __restrict__ aW2,
                              const float* __restrict__ vW1,
                              const float* __restrict__ vW2)
{
    const int stride = gridDim.x * blockDim.x;
    const int t0 = blockIdx.x * blockDim.x + threadIdx.x;
    for (int i = t0; i < NF * NH; i += stride)
        g_W1r[i] = __uint_as_float(tf32r(W1[i]));
    for (int i = t0; i < NH * NH; i += stride) {
        g_W2r[i]  = __uint_as_float(tf32r(W2[i]));
        g_aW2r[i] = __uint_as_float(tf32r(aW2[i]));
        g_vW2r[i] = __uint_as_float(tf32r(vW2[i]));
    }
    for (int i = t0; i < NH * NE; i += stride)
        g_W3r[i] = __uint_as_float(tf32r(W3[i]));
    for (int i = t0; i < 160 * NH; i += stride) {
        const int k = i >> 8, n = i & 255;
        g_aW1p[i] = (k < NE + NOWN) ? __uint_as_float(tf32r(aW1[k * NH + n])) : 0.f;
        g_vW1p[i] = (k < NE + NOWN) ? __uint_as_float(tf32r(vW1[k * NH + n])) : 0.f;
    }
}

// ===========================================================================
// common building blocks
// B smem layout: row-major [32 k x NCOLS n], pitch BPITCH -> conflict-free
// ===========================================================================
template<int NCOLS>
__device__ __forceinline__ void stage16(uint32_t bbuf, const float* __restrict__ Wg,
                                        int cc, int tid) {
    constexpr int CPR = NCOLS / 4;
    constexpr int TOT = 32 * CPR;
    #pragma unroll
    for (int i = 0; i < TOT / 256; ++i) {
        const int d  = tid + 256 * i;
        const int kr = d / CPR;
        const int cf = (d % CPR) * 4;
        cpasync16(bbuf + (uint32_t)kr * BPITCH + (uint32_t)cf * 4u,
                  Wg + (size_t)(cc * 32 + kr) * NCOLS + cf);
    }
}

// ---------------- seq variants (4 mb blocks per warp, 8 mb total) ----------
template<int NTW>
__device__ __forceinline__ void mma_kb(float (&acc)[4][NTW][4], uint32_t A_B,
                                       int kbG, int wy, uint32_t bbuf, int kb,
                                       int ntbase, int l, int g, int t) {
    uint32_t a[4][4];
    #pragma unroll
    for (int mbl = 0; mbl < 4; ++mbl)
        lds128(a[mbl], A_B + (uint32_t)((kbG * 8 + 4 * wy + mbl) * 512 + l * 16));
    const uint32_t b0row = bbuf + (uint32_t)(kb * 8 + t) * BPITCH;
    #pragma unroll
    for (int ntl = 0; ntl < NTW; ++ntl) {
        const uint32_t noff = (uint32_t)(((ntbase + ntl) * 8 + g) * 4);
        const uint32_t b0 = lds32(b0row + noff);
        const uint32_t b1 = lds32(b0row + 4u * BPITCH + noff);
        #pragma unroll
        for (int mbl = 0; mbl < 4; ++mbl)
            mma_tf32(acc[mbl][ntl], a[mbl], b0, b1);
    }
}

template<int NTW>
__device__ __forceinline__ void zacc(float (&acc)[4][NTW][4]) {
    #pragma unroll
    for (int i = 0; i < 4; ++i)
        #pragma unroll
        for (int j = 0; j < NTW; ++j) {
            acc[i][j][0] = 0.f; acc[i][j][1] = 0.f;
            acc[i][j][2] = 0.f; acc[i][j][3] = 0.f;
        }
}

template<int NTW>
__device__ __forceinline__ void epi2A(float (&acc)[4][NTW][4],
                                      const float* __restrict__ bias,
                                      uint32_t A_B, int wy, int ntbase,
                                      int g, int t) {
    const int c0 = 2 * t, c1 = 2 * t + 1;
    const uint32_t lo0 = (uint32_t)((4 * g + (c0 & 3)) * 16 + ((c0 & 4) ? 8 : 0));
    const uint32_t lo1 = (uint32_t)((4 * g + (c1 & 3)) * 16 + ((c1 & 4) ? 8 : 0));
    #pragma unroll
    for (int ntl = 0; ntl < NTW; ++ntl) {
        const int ntG = ntbase + ntl;
        const int n0  = ntG * 8 + c0;
        const float bb0 = __ldg(bias + n0), bb1 = __ldg(bias + n0 + 1);
        #pragma unroll
        for (int mbl = 0; mbl < 4; ++mbl) {
            const uint32_t base = A_B + (uint32_t)((ntG * 8 + 4 * wy + mbl) * 512);
            sts64(base + lo0, tf32r(fmaxf(acc[mbl][ntl][0] + bb0, 0.f)),
                              tf32r(fmaxf(acc[mbl][ntl][2] + bb0, 0.f)));
            sts64(base + lo1, tf32r(fmaxf(acc[mbl][ntl][1] + bb1, 0.f)),
                              tf32r(fmaxf(acc[mbl][ntl][3] + bb1, 0.f)));
        }
    }
}

// ---------------- head variants (2 mb blocks per warp, 4 mb total) ---------
__device__ __forceinline__ void mma_kb2(float (&acc)[2][8][4], uint32_t A_B,
                                        int kbG, int wy, uint32_t bbuf, int kb,
                                        int ntbase, int l, int g, int t) {
    uint32_t a[2][4];
    #pragma unroll
    for (int mbl = 0; mbl < 2; ++mbl)
        lds128(a[mbl], A_B + (uint32_t)((kbG * 4 + 2 * wy + mbl) * 512 + l * 16));
    const uint32_t b0row = bbuf + (uint32_t)(kb * 8 + t) * BPITCH;
    #pragma unroll
    for (int ntl = 0; ntl < 8; ++ntl) {
        const uint32_t noff = (uint32_t)(((ntbase + ntl) * 8 + g) * 4);
        const uint32_t b0 = lds32(b0row + noff);
        const uint32_t b1 = lds32(b0row + 4u * BPITCH + noff);
        #pragma unroll
        for (int mbl = 0; mbl < 2; ++mbl)
            mma_tf32(acc[mbl][ntl], a[mbl], b0, b1);
    }
}

__device__ __forceinline__ void zacc2(float (&acc)[2][8][4]) {
    #pragma unroll
    for (int i = 0; i < 2; ++i)
        #pragma unroll
        for (int j = 0; j < 8; ++j) {
            acc[i][j][0] = 0.f; acc[i][j][1] = 0.f;
            acc[i][j][2] = 0.f; acc[i][j][3] = 0.f;
        }
}

__device__ __forceinline__ void epi2H(float (&acc)[2][8][4],
                                      const float* __restrict__ bias,
                                      uint32_t H_B, int wy, int ntbase,
                                      int g, int t) {
    const int c0 = 2 * t, c1 = 2 * t + 1;
    const uint32_t lo0 = (uint32_t)((4 * g + (c0 & 3)) * 16 + ((c0 & 4) ? 8 : 0));
    const uint32_t lo1 = (uint32_t)((4 * g + (c1 & 3)) * 16 + ((c1 & 4) ? 8 : 0));
    #pragma unroll
    for (int ntl = 0; ntl < 8; ++ntl) {
        const int ntG = ntbase + ntl;
        const int n0  = ntG * 8 + c0;
        const float bb0 = __ldg(bias + n0), bb1 = __ldg(bias + n0 + 1);
        #pragma unroll
        for (int mbl = 0; mbl < 2; ++mbl) {
            const uint32_t base = H_B + (uint32_t)((ntG * 4 + 2 * wy + mbl) * 512);
            sts64(base + lo0, tf32r(fmaxf(acc[mbl][ntl][0] + bb0, 0.f)),
                              tf32r(fmaxf(acc[mbl][ntl][2] + bb0, 0.f)));
            sts64(base + lo1, tf32r(fmaxf(acc[mbl][ntl][1] + bb1, 0.f)),
                              tf32r(fmaxf(acc[mbl][ntl][3] + bb1, 0.f)));
        }
    }
}

// write H2 (bias+relu, FP32 — no tf32 round) into plain [64 x 260] at P_B
__device__ __forceinline__ void epi2P(float (&acc)[2][8][4],
                                      const float* __restrict__ bias,
                                      uint32_t P_B, int wy, int wx,
                                      int g, int t) {
    #pragma unroll
    for (int mbl = 0; mbl < 2; ++mbl) {
        const int m = 32 * wy + 16 * mbl + g;
        #pragma unroll
        for (int ntl = 0; ntl < 8; ++ntl) {
            const int n0 = (8 * wx + ntl) * 8 + 2 * t;
            const float bb0 = __ldg(bias + n0), bb1 = __ldg(bias + n0 + 1);
            sts64(P_B + (uint32_t)((m * 260 + n0) * 4),
                  __float_as_uint(fmaxf(acc[mbl][ntl][0] + bb0, 0.f)),
                  __float_as_uint(fmaxf(acc[mbl][ntl][1] + bb1, 0.f)));
            sts64(P_B + (uint32_t)(((m + 8) * 260 + n0) * 4),
                  __float_as_uint(fmaxf(acc[mbl][ntl][2] + bb0, 0.f)),
                  __float_as_uint(fmaxf(acc[mbl][ntl][3] + bb1, 0.f)));
        }
    }
}

// MLP (L1 K=160 from cat frag, relu -> H frag, L2 K=256) ; result raw in acc.
// Precondition: W1p chunk 0 already staged into HB buf0 and committed.
__device__ __forceinline__ void head_mlp2(uint32_t HC, uint32_t HH, uint32_t HB,
                                          const float* __restrict__ W1p,
                                          const float* __restrict__ b1h,
                                          const float* __restrict__ W2r,
                                          float (&acc)[2][8][4],
                                          int tid, int wy, int wx,
                                          int l, int g, int t) {
    zacc2(acc);
    for (int cc = 0; cc < 5; ++cc) {
        if (cc < 4) {
            stage16<256>(HB + (uint32_t)((cc + 1) & 1) * BBUF_SZ, W1p, cc + 1, tid);
            CP_COMMIT();
            CP_WAIT(1);
        } else {
            CP_WAIT(0);
        }
        __syncthreads();
        const uint32_t bb = HB + (uint32_t)(cc & 1) * BBUF_SZ;
        #pragma unroll
        for (int kb = 0; kb < 4; ++kb)
            mma_kb2(acc, HC, cc * 4 + kb, wy, bb, kb, 8 * wx, l, g, t);
        __syncthreads();
    }
    stage16<256>(HB, W2r, 0, tid);   // chunk 0 -> buf0 (cc=4 used buf0; done)
    CP_COMMIT();
    epi2H(acc, b1h, HH, wy, 8 * wx, g, t);
    zacc2(acc);
    __syncthreads();
    for (int cc = 0; cc < 8; ++cc) {
        if (cc < 7) {
            stage16<256>(HB + (uint32_t)((cc + 1) & 1) * BBUF_SZ, W2r, cc + 1, tid);
            CP_COMMIT();
            CP_WAIT(1);
        } else {
            CP_WAIT(0);
        }
        __syncthreads();
        const uint32_t bb = HB + (uint32_t)(cc & 1) * BBUF_SZ;
        #pragma unroll
        for (int kb = 0; kb < 4; ++kb)
            mma_kb2(acc, HH, cc * 4 + kb, wy, bb, kb, 8 * wx, l, g, t);
        __syncthreads();
    }
}

// ===========================================================================
// Kernel 1: tf32 mma.sync token encoder (unchanged from round 8, ~820us)
// ===========================================================================
__global__ void __launch_bounds__(256, 1)
seq_tc(const float* __restrict__ obs,
       const float* __restrict__ b1,
       const float* __restrict__ b2,
       const float* __restrict__ b3)
{
    extern __shared__ float sm[];
    const int tid = threadIdx.x;
    const int w = tid >> 5, l = tid & 31;
    const int g = l >> 2, t = l & 3;
    const int wy = w >> 2, wx = w & 3;
    const uint32_t sb   = smem_u32(sm);
    const uint32_t A_B  = sb;
    const uint32_t W1_B = sb + OFF_W1;
    const uint32_t B_B  = sb + OFF_B;
    float* maskS = sm + (OFF_MASK / 4);
    float* Ps    = sm + (OFF_B / 4);

    for (int d = tid; d < 1088; d += 256) {
        const int kr = d >> 6, cf = (d & 63) * 4;
        cpasync16(W1_B + (uint32_t)kr * BPITCH + (uint32_t)cf * 4u,
                  g_W1r + (size_t)kr * 256 + cf);
    }
    CP_COMMIT();
    for (int d = tid; d < 1848; d += 256)
        STS32(W1_B + 17u * BPITCH + (uint32_t)d * 4u, 0u);
    CP_WAIT(0);
    __syncthreads();

    for (int tt = blockIdx.x; tt < NTILES; tt += gridDim.x) {
        const int b0 = 3 * tt;

        if (tid < 128) {
            const int r = tid;
            float xv[24];
            #pragma unroll
            for (int c = 0; c < 24; ++c) xv[c] = 0.f;
            float s = 0.f; bool valid = false;
            if (r < 111) {
                const int j = r / 37, ss2 = r - 37 * j;
                if (b0 + j < NB) {
                    const float* xg = obs + ((size_t)(b0 + j) * 38 + 1 + ss2) * NF;
                    #pragma unroll
                    for (int c = 0; c < NF; ++c) { xv[c] = xg[c]; s += fabsf(xv[c]); }
                    valid = true;
                }
            }
            maskS[r] = (valid && s != 0.f) ? 1.f : 0.f;
            const int mb = r >> 4, rg = r & 7, rhi = (r >> 3) & 1;
            #pragma unroll
            for (int c = 0; c < 24; ++c) {
                const int kb = c >> 3, lane = 4 * rg + (c & 3);
                const int slot = (((c & 7) >> 2) << 1) + rhi;
                STS32(A_B + (uint32_t)((kb * 8 + mb) * 512 + lane * 16 + slot * 4),
                      tf32r(xv[c]));
            }
        }
        stage16<256>(B_B, g_W2r, 0, tid);
        CP_COMMIT();
        __syncthreads();

        float acc[4][8][4];
        zacc<8>(acc);
        #pragma unroll
        for (int kb = 0; kb < 3; ++kb)
            mma_kb<8>(acc, A_B, kb, wy, W1_B, kb, 8 * wx, l, g, t);
        __syncthreads();
        epi2A<8>(acc, b1, A_B, wy, 8 * wx, g, t);
        __syncthreads();

        zacc<8>(acc);
        for (int cc = 0; cc < 8; ++cc) {
            if (cc < 7) {
                stage16<256>(B_B + (uint32_t)((cc + 1) & 1) * BBUF_SZ, g_W2r, cc + 1, tid);
                CP_COMMIT();
                CP_WAIT(1);
            } else {
                CP_WAIT(0);
            }
            __syncthreads();
            const uint32_t bb = B_B + (uint32_t)(cc & 1) * BBUF_SZ;
            #pragma unroll
            for (int kb = 0; kb < 4; ++kb)
                mma_kb<8>(acc, A_B, cc * 4 + kb, wy, bb, kb, 8 * wx, l, g, t);
            __syncthreads();
        }
        stage16<128>(B_B, g_W3r, 0, tid);
        CP_COMMIT();
        epi2A<8>(acc, b2, A_B, wy, 8 * wx, g, t);
        __syncthreads();

        float acc3[4][4][4];
        zacc<4>(acc3);
        for (int cc = 0; cc < 8; ++cc) {
            if (cc < 7) {
                stage16<128>(B_B + (uint32_t)((cc + 1) & 1) * BBUF_SZ, g_W3r, cc + 1, tid);
                CP_COMMIT();
                CP_WAIT(1);
            } else {
                CP_WAIT(0);
            }
            __syncthreads();
            const uint32_t bb = B_B + (uint32_t)(cc & 1) * BBUF_SZ;
            #pragma unroll
            for (int kb = 0; kb < 4; ++kb)
                mma_kb<4>(acc3, A_B, cc * 4 + kb, wy, bb, kb, 4 * wx, l, g, t);
            __syncthreads();
        }

        #pragma unroll
        for (int mbl = 0; mbl < 4; ++mbl) {
            const int m = 64 * wy + 16 * mbl + g;
            const float mk0 = maskS[m], mk1 = maskS[m + 8];
            #pragma unroll
            for (int ntl = 0; ntl < 4; ++ntl) {
                const int n0 = (4 * wx + ntl) * 8 + 2 * t;
                const float bb0 = __ldg(b3 + n0), bb1 = __ldg(b3 + n0 + 1);
                const float p00 = mk0 * fmaxf(acc3[mbl][ntl][0] + bb0, 0.f);
                const float p01 = mk0 * fmaxf(acc3[mbl][ntl][1] + bb1, 0.f);
                const float p10 = mk1 * fmaxf(acc3[mbl][ntl][2] + bb0, 0.f);
                const float p11 = mk1 * fmaxf(acc3[mbl][ntl][3] + bb1, 0.f);
                sts64(B_B + (uint32_t)((m * 132 + n0) * 4),
                      __float_as_uint(p00), __float_as_uint(p01));
                sts64(B_B + (uint32_t)(((m + 8) * 132 + n0) * 4),
                      __float_as_uint(p10), __float_as_uint(p11));
            }
        }
        __syncthreads();
        for (int idx = tid; idx < 384; idx += 256) {
            const int j = idx >> 7, c = idx & 127;
            if (b0 + j < NB) {
                float s = 0.f;
                const float* base = Ps + (size_t)(37 * j) * 132 + c;
                #pragma unroll 37
                for (int ss2 = 0; ss2 < 37; ++ss2) s += base[ss2 * 132];
                g_summed[(size_t)(b0 + j) * NE + c] = s;
            }
        }
        __syncthreads();
    }
}

// ===========================================================================
// Kernel 2: tensorized actor + value heads. 64 batch rows per CTA, grid 256.
// ===========================================================================
__global__ void __launch_bounds__(256, 1)
head_tc(const float* __restrict__ obs,
        const float* __restrict__ ab1, const float* __restrict__ ab2,
        const float* __restrict__ aW3, const float* __restrict__ ab3,
        const float* __restrict__ vb1, const float* __restrict__ vb2,
        const float* __restrict__ vW3, const float* __restrict__ vb3,
        float* __restrict__ out)
{
    extern __shared__ float sm[];
    const int tid = threadIdx.x;
    const int w = tid >> 5, l = tid & 31;
    const int g = l >> 2, t = l & 3;
    const int wy = w >> 2, wx = w & 3;
    const uint32_t sb = smem_u32(sm);
    const uint32_t HC = sb;                 // cat frag
    const uint32_t HH = sb + HOFF_H;        // H frag / aW3 plain
    const uint32_t HB = sb + HOFF_B;        // B bufs / H2 plain
    float* Wa3 = sm + (HOFF_H / 4);         // aW3 plain view
    float* Pp  = sm + (HOFF_B / 4);         // H2 plain view [64 x 260]
    const int m0 = blockIdx.x * 64;

    // ---- stage cat = [summed(128) | own(9) | 0...] into frag (K=160) ----
    {
        const int r = tid >> 2;           // 0..63
        const int part = tid & 3;         // 40 cols each
        const int row = m0 + r;
        const int mb = r >> 4, rg = r & 7, r8 = (r >> 3) & 1;
        for (int c = part * 40; c < part * 40 + 40; ++c) {
            float v = 0.f;
            if (c < NE)             v = g_summed[(size_t)row * NE + c];
            else if (c < NE + NOWN) v = __ldg(&obs[(size_t)row * 38 * NF + (c - NE)]);
            const int kb = c >> 3, tc = c & 3, k4 = (c >> 2) & 1;
            STS32(HC + (uint32_t)((kb * 4 + mb) * 512 + (4 * rg + tc) * 16
                                  + (2 * k4 + r8) * 4), tf32r(v));
        }
    }
    stage16<256>(HB, g_aW1p, 0, tid);
    CP_COMMIT();
    __syncthreads();

    float acc[2][8][4];

    // ================= actor MLP (L1+L2), result raw in acc ================
    head_mlp2(HC, HH, HB, g_aW1p, ab1, g_aW2r, acc, tid, wy, wx, l, g, t);

    // aH2 (fp32, relu) -> plain in B region
    epi2P(acc, ab2, HB, wy, wx, g, t);
    __syncthreads();

    // stage aW3 [256 x 23] into H region (H frag no longer needed)
    for (int e = tid; e < 256 * NOUT; e += 256)
        STS32(HH + (uint32_t)e * 4u, __float_as_uint(__ldg(&aW3[e])));
    __syncthreads();

    // ---- logits (fp32 scalar): rows w + 8i, lane = output j ----
    const int tx = l;
    if (tx < NOUT) {
        float accL[8];
        const float bb = __ldg(&ab3[tx]);
        #pragma unroll
        for (int i = 0; i < 8; ++i) accL[i] = bb;
        for (int k = 0; k < 256; k += 4) {
            const float wv0 = Wa3[(k + 0) * NOUT + tx];
            const float wv1 = Wa3[(k + 1) * NOUT + tx];
            const float wv2 = Wa3[(k + 2) * NOUT + tx];
            const float wv3 = Wa3[(k + 3) * NOUT + tx];
            #pragma unroll
            for (int i = 0; i < 8; ++i) {
                const float4 h = *(const float4*)(Pp + (w + 8 * i) * 260 + k);
                accL[i] += h.x * wv0 + h.y * wv1 + h.z * wv2 + h.w * wv3;
            }
        }
        #pragma unroll
        for (int i = 0; i < 8; ++i)
            out[(size_t)(m0 + w + 8 * i) * NOUT + tx] = accL[i];
    }
    __syncthreads();

    // ================= value MLP (L1+L2) ==================================
    stage16<256>(HB, g_vW1p, 0, tid);
    CP_COMMIT();
    head_mlp2(HC, HH, HB, g_vW1p, vb1, g_vW2r, acc, tid, wy, wx, l, g, t);

    // vH2 (fp32, relu) -> plain in B region
    epi2P(acc, vb2, HB, wy, wx, g, t);
    __syncthreads();

    // ---- value (fp32 scalar dot + warp reduce): rows w + 8i ----
    {
        float accV[8];
        #pragma unroll
        for (int i = 0; i < 8; ++i) accV[i] = 0.f;
        for (int k = l; k < 256; k += 32) {
            const float wv = __ldg(&vW3[k]);
            #pragma unroll
            for (int i = 0; i < 8; ++i)
                accV[i] += Pp[(w + 8 * i) * 260 + k] * wv;
        }
        #pragma unroll
        for (int off = 16; off; off >>= 1) {
            #pragma unroll
            for (int i = 0; i < 8; ++i)
                accV[i] += __shfl_xor_sync(0xffffffffu, accV[i], off);
        }
        if (l == 0) {
            const float bb = __ldg(&vb3[0]);
            #pragma unroll
            for (int i = 0; i < 8; ++i)
                out[(size_t)NB * NOUT + m0 + w + 8 * i] = accV[i] + bb;
        }
    }
}

// ===========================================================================
extern "C" void kernel_launch(void* const* d_in, const int* in_sizes, int n_in,
                              void* d_out, int out_size)
{
    const float* obs = (const float*)d_in[0];
    const float* sW1 = (const float*)d_in[1];
    const float* sb1 = (const float*)d_in[2];
    const float* sW2 = (const float*)d_in[3];
    const float* sb2 = (const float*)d_in[4];
    const float* sW3 = (const float*)d_in[5];
    const float* sb3 = (const float*)d_in[6];
    const float* aW1 = (const float*)d_in[7];
    const float* ab1 = (const float*)d_in[8];
    const float* aW2 = (const float*)d_in[9];
    const float* ab2 = (const float*)d_in[10];
    const float* aW3 = (const float*)d_in[11];
    const float* ab3 = (const float*)d_in[12];
    const float* vW1 = (const float*)d_in[13];
    const float* vb1 = (const float*)d_in[14];
    const float* vW2 = (const float*)d_in[15];
    const float* vb2 = (const float*)d_in[16];
    const float* vW3 = (const float*)d_in[17];
    const float* vb3 = (const float*)d_in[18];
    float* out = (float*)d_out;

    cudaFuncSetAttribute(seq_tc,  cudaFuncAttributeMaxDynamicSharedMemorySize, SMEM_TC);
    cudaFuncSetAttribute(head_tc, cudaFuncAttributeMaxDynamicSharedMemorySize, SMEM_HD);

    round_weights<<<128, 256>>>(sW1, sW2, sW3, aW1, aW2, vW1, vW2);
    seq_tc<<<152, 256, SMEM_TC>>>(obs, sb1, sb2, sb3);
    head_tc<<<NB / 64, 256, SMEM_HD>>>(obs, ab1, ab2, aW3, ab3,
                                       vb1, vb2, vW3, vb3, out);
}

// round 10
// speedup vs baseline: 5.3489x; 1.6051x over previous
#include <cuda_runtime.h>
#include <cuda_fp16.h>
#include <cstdint>

// Problem constants
#define NB   16384
#define NS   37
#define NF   17
#define NOWN 9
#define NH   256
#define NE   128
#define NOUT 23
#define NTILES ((NB + 2) / 3)   // 5462 tiles of 3 batch elements

// scratch: pooled encoder output per batch row
__device__ float g_summed[(size_t)NB * NE];
// packed fp16 (RN) weights: u32 = half2 {lo = k even, hi = k odd}, layout [kp][n]
__device__ uint32_t g_W1h[16 * 256];     // k 0..31 (zeros >= 17)
__device__ uint32_t g_W2h[128 * 256];
__device__ uint32_t g_W3h[128 * 128];
__device__ uint32_t g_aW1h[80 * 256];    // k 0..159 (zeros >= 137)
__device__ uint32_t g_vW1h[80 * 256];
__device__ uint32_t g_aW2h[128 * 256];
__device__ uint32_t g_vW2h[128 * 256];

// ===========================================================================
// seq_tc smem layout (bytes):
//   A frag : 16 K16-blocks x 8 mb x 512 = 65536 @ 0
//   B bufs : 2 x 16 kp-rows x 1056      = 33792 @ 65536
//   W1     : 16 kp-rows x 1056          = 16896 @ 99328  (persistent)
//   mask   : 128 f32                    =   512 @ 116224
//   (Ps pool buffer 128x132 f32 = 67584 overlays A + start of B, used
//    only after L3 MMAs complete)
// ===========================================================================
#define OFF_B    65536u
#define OFF_W1   99328u
#define OFF_MASK 116224u
#define SMEM_TC  116736
#define BPITCH   1056u
#define BBUF_SZ  16896u

// head_tc smem layout:
//   cat frag : 10 K16-blocks x 4 mb x 512 = 20480 @ 0
//   H frag   : 16 K16-blocks x 4 mb x 512 = 32768 @ 20480  (also aW3 plain)
//   B bufs   : 2 x 16896 = 33792           @ 53248
//   H2 plain : 64 x 260 f32 = 66560        @ 87040
#define HOFF_HH  20480u
#define HOFF_B   53248u
#define HOFF_P   87040u
#define SMEM_HD  153600

// ===========================================================================
// PTX helpers
// ===========================================================================
__device__ __forceinline__ uint32_t smem_u32(const void* p) {
    uint32_t a;
    asm("{ .reg .u64 t; cvta.to.shared.u64 t, %1; cvt.u32.u64 %0, t; }"
        : "=r"(a) : "l"(p));
    return a;
}
__device__ __forceinline__ uint32_t packh2(float e, float o) {
    __half2 h = __floats2half2_rn(e, o);
    return *reinterpret_cast<uint32_t*>(&h);
}
__device__ __forceinline__ void lds128(uint32_t r[4], uint32_t a) {
    asm volatile("ld.shared.v4.b32 {%0,%1,%2,%3}, [%4];"
                 : "=r"(r[0]), "=r"(r[1]), "=r"(r[2]), "=r"(r[3]) : "r"(a));
}
__device__ __forceinline__ uint32_t lds32(uint32_t a) {
    uint32_t v; asm volatile("ld.shared.b32 %0, [%1];" : "=r"(v) : "r"(a)); return v;
}
__device__ __forceinline__ void sts64(uint32_t a, uint32_t v0, uint32_t v1) {
    asm volatile("st.shared.v2.b32 [%0], {%1,%2};" :: "r"(a), "r"(v0), "r"(v1));
}
#define STS32(a, v) asm volatile("st.shared.b32 [%0], %1;" :: "r"(a), "r"(v) : "memory")

__device__ __forceinline__ void cpasync16(uint32_t dst, const void* g) {
    asm volatile("cp.async.cg.shared.global [%0], [%1], 16;"
                 :: "r"(dst), "l"(__cvta_generic_to_global(g)) : "memory");
}
#define CP_COMMIT() asm volatile("cp.async.commit_group;" ::: "memory")
#define CP_WAIT(n)  asm volatile("cp.async.wait_group %0;" :: "n"(n) : "memory")

// mma.sync m16n8k16 fp16 (fp32 accum). Frags (lane: g=l>>2, t=l&3):
//  a0={A[g][2t],A[g][2t+1]} a1={A[g+8][..]} a2={A[g][2t+8],..} a3={A[g+8][2t+8],..}
//  b0={B[2t][n g],B[2t+1][g]} b1={B[2t+8][g],B[2t+9][g]}
//  c0=D[g][2t] c1=D[g][2t+1] c2=D[g+8][2t] c3=D[g+8][2t+1]
__device__ __forceinline__ void mma_f16(float d[4], const uint32_t a[4],
                                        uint32_t b0, uint32_t b1) {
    asm volatile(
        "mma.sync.aligned.m16n8k16.row.col.f32.f16.f16.f32 "
        "{%0,%1,%2,%3}, {%4,%5,%6,%7}, {%8,%9}, {%0,%1,%2,%3};"
        : "+f"(d[0]), "+f"(d[1]), "+f"(d[2]), "+f"(d[3])
        : "r"(a[0]), "r"(a[1]), "r"(a[2]), "r"(a[3]), "r"(b0), "r"(b1));
}

// ===========================================================================
// Kernel 0: pack all MMA weights to fp16 pairs (RN), with K zero-padding
// ===========================================================================
__global__ void round_weights(const float* __restrict__ W1,
                              const float* __restrict__ W2,
                              const float* __restrict__ W3,
                              const float* __restrict__ aW1,
                              const float* __restrict__ aW2,
                              const float* __restrict__ vW1,
                              const float* __restrict__ vW2)
{
    const int stride = gridDim.x * blockDim.x;
    const int t0 = blockIdx.x * blockDim.x + threadIdx.x;
    for (int i = t0; i < 16 * 256; i += stride) {
        const int kp = i >> 8, n = i & 255;
        const float e = (2 * kp     < NF) ? W1[(2 * kp) * 256 + n]     : 0.f;
        const float o = (2 * kp + 1 < NF) ? W1[(2 * kp + 1) * 256 + n] : 0.f;
        g_W1h[i] = packh2(e, o);
    }
    for (int i = t0; i < 128 * 256; i += stride) {
        const int kp = i >> 8, n = i & 255;
        g_W2h[i]  = packh2(W2[(2 * kp) * 256 + n],  W2[(2 * kp + 1) * 256 + n]);
        g_aW2h[i] = packh2(aW2[(2 * kp) * 256 + n], aW2[(2 * kp + 1) * 256 + n]);
        g_vW2h[i] = packh2(vW2[(2 * kp) * 256 + n], vW2[(2 * kp + 1) * 256 + n]);
    }
    for (int i = t0; i < 128 * 128; i += stride) {
        const int kp = i >> 7, n = i & 127;
        g_W3h[i] = packh2(W3[(2 * kp) * 128 + n], W3[(2 * kp + 1) * 128 + n]);
    }
    for (int i = t0; i < 80 * 256; i += stride) {
        const int kp = i >> 8, n = i & 255;
        const int k0 = 2 * kp, k1 = 2 * kp + 1;
        const float ae = (k0 < NE + NOWN) ? aW1[k0 * 256 + n] : 0.f;
        const float ao = (k1 < NE + NOWN) ? aW1[k1 * 256 + n] : 0.f;
        const float ve = (k0 < NE + NOWN) ? vW1[k0 * 256 + n] : 0.f;
        const float vo = (k1 < NE + NOWN) ? vW1[k1 * 256 + n] : 0.f;
        g_aW1h[i] = packh2(ae, ao);
        g_vW1h[i] = packh2(ve, vo);
    }
}

// ===========================================================================
// common building blocks
// B smem: [16 kp-rows x NCOLS u32] per chunk, pitch BPITCH -> conflict-free
// one chunk = 32 k values = 2 K16 MMA steps
// ===========================================================================
template<int NCOLS>
__device__ __forceinline__ void stageh(uint32_t bbuf, const uint32_t* __restrict__ Wg,
                                       int cc, int tid) {
    constexpr int CPR = NCOLS / 4;          // 16B units per kp-row
    constexpr int TOT = 16 * CPR;
    #pragma unroll
    for (int i = 0; i < TOT / 256; ++i) {
        const int d  = tid + 256 * i;
        const int kr = d / CPR;
        const int cf = (d % CPR) * 4;
        cpasync16(bbuf + (uint32_t)kr * BPITCH + (uint32_t)cf * 4u,
                  Wg + (size_t)(cc * 16 + kr) * NCOLS + cf);
    }
}

// ---------------- seq (8 mb blocks, warp owns 4) ---------------------------
template<int NTW>
__device__ __forceinline__ void mma_kb(float (&acc)[4][NTW][4], uint32_t A_B,
                                       int sG, int wy, uint32_t bbuf, int sl,
                                       int ntbase, int l, int g, int t) {
    uint32_t a[4][4];
    #pragma unroll
    for (int mbl = 0; mbl < 4; ++mbl)
        lds128(a[mbl], A_B + (uint32_t)((sG * 8 + 4 * wy + mbl) * 512 + l * 16));
    const uint32_t b0row = bbuf + (uint32_t)(sl * 8 + t) * BPITCH;
    #pragma unroll
    for (int ntl = 0; ntl < NTW; ++ntl) {
        const uint32_t noff = (uint32_t)(((ntbase + ntl) * 8 + g) * 4);
        const uint32_t b0 = lds32(b0row + noff);
        const uint32_t b1 = lds32(b0row + 4u * BPITCH + noff);
        #pragma unroll
        for (int mbl = 0; mbl < 4; ++mbl)
            mma_f16(acc[mbl][ntl], a[mbl], b0, b1);
    }
}

template<int NTW>
__device__ __forceinline__ void zacc(float (&acc)[4][NTW][4]) {
    #pragma unroll
    for (int i = 0; i < 4; ++i)
        #pragma unroll
        for (int j = 0; j < NTW; ++j) {
            acc[i][j][0] = 0.f; acc[i][j][1] = 0.f;
            acc[i][j][2] = 0.f; acc[i][j][3] = 0.f;
        }
}

// bias + relu + fp16-pack, write back into A frag (seq: 8 mb blocks)
__device__ __forceinline__ void epi2A(float (&acc)[4][8][4],
                                      const float* __restrict__ bias,
                                      uint32_t A_B, int wy, int ntbase,
                                      int g, int t) {
    #pragma unroll
    for (int ntl = 0; ntl < 8; ++ntl) {
        const int ntG = ntbase + ntl;
        const int n0  = ntG * 8 + 2 * t;
        const float bb0 = __ldg(bias + n0), bb1 = __ldg(bias + n0 + 1);
        const uint32_t hoff = (uint32_t)((ntG & 1) * 8);
        #pragma unroll
        for (int mbl = 0; mbl < 4; ++mbl) {
            const uint32_t v01 = packh2(fmaxf(acc[mbl][ntl][0] + bb0, 0.f),
                                        fmaxf(acc[mbl][ntl][1] + bb1, 0.f));
            const uint32_t v23 = packh2(fmaxf(acc[mbl][ntl][2] + bb0, 0.f),
                                        fmaxf(acc[mbl][ntl][3] + bb1, 0.f));
            const uint32_t addr = A_B
                + (uint32_t)(((ntG >> 1) * 8 + 4 * wy + mbl) * 512)
                + (uint32_t)((4 * g + t) * 16) + hoff;
            sts64(addr, v01, v23);
        }
    }
}

// ---------------- head (4 mb blocks, warp owns 2) --------------------------
__device__ __forceinline__ void mma_kb2(float (&acc)[2][8][4], uint32_t A_B,
                                        int sG, int wy, uint32_t bbuf, int sl,
                                        int ntbase, int l, int g, int t) {
    uint32_t a[2][4];
    #pragma unroll
    for (int mbl = 0; mbl < 2; ++mbl)
        lds128(a[mbl], A_B + (uint32_t)((sG * 4 + 2 * wy + mbl) * 512 + l * 16));
    const uint32_t b0row = bbuf + (uint32_t)(sl * 8 + t) * BPITCH;
    #pragma unroll
    for (int ntl = 0; ntl < 8; ++ntl) {
        const uint32_t noff = (uint32_t)(((ntbase + ntl) * 8 + g) * 4);
        const uint32_t b0 = lds32(b0row + noff);
        const uint32_t b1 = lds32(b0row + 4u * BPITCH + noff);
        #pragma unroll
        for (int mbl = 0; mbl < 2; ++mbl)
            mma_f16(acc[mbl][ntl], a[mbl], b0, b1);
    }
}

__device__ __forceinline__ void zacc2(float (&acc)[2][8][4]) {
    #pragma unroll
    for (int i = 0; i < 2; ++i)
        #pragma unroll
        for (int j = 0; j < 8; ++j) {
            acc[i][j][0] = 0.f; acc[i][j][1] = 0.f;
            acc[i][j][2] = 0.f; acc[i][j][3] = 0.f;
        }
}

__device__ __forceinline__ void epi2H(float (&acc)[2][8][4],
                                      const float* __restrict__ bias,
                                      uint32_t H_B, int wy, int ntbase,
                                      int g, int t) {
    #pragma unroll
    for (int ntl = 0; ntl < 8; ++ntl) {
        const int ntG = ntbase + ntl;
        const int n0  = ntG * 8 + 2 * t;
        const float bb0 = __ldg(bias + n0), bb1 = __ldg(bias + n0 + 1);
        const uint32_t hoff = (uint32_t)((ntG & 1) * 8);
        #pragma unroll
        for (int mbl = 0; mbl < 2; ++mbl) {
            const uint32_t v01 = packh2(fmaxf(acc[mbl][ntl][0] + bb0, 0.f),
                                        fmaxf(acc[mbl][ntl][1] + bb1, 0.f));
            const uint32_t v23 = packh2(fmaxf(acc[mbl][ntl][2] + bb0, 0.f),
                                        fmaxf(acc[mbl][ntl][3] + bb1, 0.f));
            const uint32_t addr = H_B
                + (uint32_t)(((ntG >> 1) * 4 + 2 * wy + mbl) * 512)
                + (uint32_t)((4 * g + t) * 16) + hoff;
            sts64(addr, v01, v23);
        }
    }
}

// write H2 (bias+relu, FP32) into plain [64 x 260] at P_B
__device__ __forceinline__ void epi2P(float (&acc)[2][8][4],
                                      const float* __restrict__ bias,
                                      uint32_t P_B, int wy, int wx,
                                      int g, int t) {
    #pragma unroll
    for (int mbl = 0; mbl < 2; ++mbl) {
        const int m = 32 * wy + 16 * mbl + g;
        #pragma unroll
        for (int ntl = 0; ntl < 8; ++ntl) {
            const int n0 = (8 * wx + ntl) * 8 + 2 * t;
            const float bb0 = __ldg(bias + n0), bb1 = __ldg(bias + n0 + 1);
            sts64(P_B + (uint32_t)((m * 260 + n0) * 4),
                  __float_as_uint(fmaxf(acc[mbl][ntl][0] + bb0, 0.f)),
                  __float_as_uint(fmaxf(acc[mbl][ntl][1] + bb1, 0.f)));
            sts64(P_B + (uint32_t)(((m + 8) * 260 + n0) * 4),
                  __float_as_uint(fmaxf(acc[mbl][ntl][2] + bb0, 0.f)),
                  __float_as_uint(fmaxf(acc[mbl][ntl][3] + bb1, 0.f)));
        }
    }
}

// head MLP: L1 (K=160, 5 chunks) -> relu H frag -> L2 (K=256, 8 chunks)
// Precondition: W1h chunk 0 staged into HB buf0 and committed.
__device__ __forceinline__ void head_mlp2(uint32_t HC, uint32_t HH, uint32_t HB,
                                          const uint32_t* __restrict__ W1h,
                                          const float* __restrict__ b1h,
                                          const uint32_t* __restrict__ W2h,
                                          float (&acc)[2][8][4],
                                          int tid, int wy, int wx,
                                          int l, int g, int t) {
    zacc2(acc);
    for (int cc = 0; cc < 5; ++cc) {
        if (cc < 4) {
            stageh<256>(HB + (uint32_t)((cc + 1) & 1) * BBUF_SZ, W1h, cc + 1, tid);
            CP_COMMIT();
            CP_WAIT(1);
        } else {
            CP_WAIT(0);
        }
        __syncthreads();
        const uint32_t bb = HB + (uint32_t)(cc & 1) * BBUF_SZ;
        #pragma unroll
        for (int sl = 0; sl < 2; ++sl)
            mma_kb2(acc, HC, cc * 2 + sl, wy, bb, sl, 8 * wx, l, g, t);
        __syncthreads();
    }
    stageh<256>(HB, W2h, 0, tid);
    CP_COMMIT();
    epi2H(acc, b1h, HH, wy, 8 * wx, g, t);
    zacc2(acc);
    __syncthreads();
    for (int cc = 0; cc < 8; ++cc) {
        if (cc < 7) {
            stageh<256>(HB + (uint32_t)((cc + 1) & 1) * BBUF_SZ, W2h, cc + 1, tid);
            CP_COMMIT();
            CP_WAIT(1);
        } else {
            CP_WAIT(0);
        }
        __syncthreads();
        const uint32_t bb = HB + (uint32_t)(cc & 1) * BBUF_SZ;
        #pragma unroll
        for (int sl = 0; sl < 2; ++sl)
            mma_kb2(acc, HH, cc * 2 + sl, wy, bb, sl, 8 * wx, l, g, t);
        __syncthreads();
    }
}

// ===========================================================================
// Kernel 1: fp16 mma.sync token encoder. Persistent, 1 CTA/SM, 256 threads.
// Tile = 3 batch elements (111 token rows) padded to M=128.
// ===========================================================================
__global__ void __launch_bounds__(256, 1)
seq_tc(const float* __restrict__ obs,
       const float* __restrict__ b1,
       const float* __restrict__ b2,
       const float* __restrict__ b3)
{
    extern __shared__ float sm[];
    const int tid = threadIdx.x;
    const int w = tid >> 5, l = tid & 31;
    const int g = l >> 2, t = l & 3;
    const int wy = w >> 2, wx = w & 3;
    const uint32_t sb   = smem_u32(sm);
    const uint32_t A_B  = sb;
    const uint32_t B_B  = sb + OFF_B;
    const uint32_t W1_B = sb + OFF_W1;
    float* maskS = sm + (OFF_MASK / 4);
    float* Ps    = sm;                       // pool buffer overlays A (+B head)

    // ---- persistent W1 fp16 staging (16 kp rows, zeros baked in) ----
    stageh<256>(W1_B, g_W1h, 0, tid);
    CP_COMMIT();
    CP_WAIT(0);
    __syncthreads();

    for (int tt = blockIdx.x; tt < NTILES; tt += gridDim.x) {
        const int b0 = 3 * tt;

        // ---- stage X into A frag blocks 0..1 (K=32 padded), compute mask ----
        if (tid < 128) {
            const int r = tid;
            float xv[32];
            #pragma unroll
            for (int c = 0; c < 32; ++c) xv[c] = 0.f;
            float s = 0.f; bool valid = false;
            if (r < 111) {
                const int j = r / 37, ss2 = r - 37 * j;
                if (b0 + j < NB) {
                    const float* xg = obs + ((size_t)(b0 + j) * 38 + 1 + ss2) * NF;
                    #pragma unroll
                    for (int c = 0; c < NF; ++c) { xv[c] = xg[c]; s += fabsf(xv[c]); }
                    valid = true;
                }
            }
            maskS[r] = (valid && s != 0.f) ? 1.f : 0.f;
            const int mb = r >> 4, rr = r & 15, rg = rr & 7, hi8 = rr >> 3;
            #pragma unroll
            for (int cp = 0; cp < 16; ++cp) {
                const int c = 2 * cp;
                const int kb16 = c >> 4, p = cp & 7;
                const int lane = 4 * rg + (p & 3);
                const int ws = (p >> 2) * 2 + hi8;
                STS32(A_B + (uint32_t)((kb16 * 8 + mb) * 512 + lane * 16 + ws * 4),
                      packh2(xv[c], xv[c + 1]));
            }
        }
        stageh<256>(B_B, g_W2h, 0, tid);     // prefetch W2 chunk 0
        CP_COMMIT();
        __syncthreads();

        // ---- Layer 1: H1 = relu(X @ W1 + b1)  (K=32, 2 steps) ----
        float acc[4][8][4];
        zacc<8>(acc);
        #pragma unroll
        for (int sl = 0; sl < 2; ++sl)
            mma_kb<8>(acc, A_B, sl, wy, W1_B, sl, 8 * wx, l, g, t);
        __syncthreads();
        epi2A(acc, b1, A_B, wy, 8 * wx, g, t);
        __syncthreads();

        // ---- Layer 2: H2 = relu(H1 @ W2 + b2)  (K=256, 8 chunks x 2 steps) --
        zacc<8>(acc);
        for (int cc = 0; cc < 8; ++cc) {
            if (cc < 7) {
                stageh<256>(B_B + (uint32_t)((cc + 1) & 1) * BBUF_SZ, g_W2h, cc + 1, tid);
                CP_COMMIT();
                CP_WAIT(1);
            } else {
                CP_WAIT(0);
            }
            __syncthreads();
            const uint32_t bb = B_B + (uint32_t)(cc & 1) * BBUF_SZ;
            #pragma unroll
            for (int sl = 0; sl < 2; ++sl)
                mma_kb<8>(acc, A_B, cc * 2 + sl, wy, bb, sl, 8 * wx, l, g, t);
            __syncthreads();
        }
        stageh<128>(B_B, g_W3h, 0, tid);     // prefetch W3 chunk 0
        CP_COMMIT();
        epi2A(acc, b2, A_B, wy, 8 * wx, g, t);
        __syncthreads();

        // ---- Layer 3: H3 = H2 @ W3 + b3  (K=256, N=128) ----
        float acc3[4][4][4];
        zacc<4>(acc3);
        for (int cc = 0; cc < 8; ++cc) {
            if (cc < 7) {
                stageh<128>(B_B + (uint32_t)((cc + 1) & 1) * BBUF_SZ, g_W3h, cc + 1, tid);
                CP_COMMIT();
                CP_WAIT(1);
            } else {
                CP_WAIT(0);
            }
            __syncthreads();
            const uint32_t bb = B_B + (uint32_t)(cc & 1) * BBUF_SZ;
            #pragma unroll
            for (int sl = 0; sl < 2; ++sl)
                mma_kb<4>(acc3, A_B, cc * 2 + sl, wy, bb, sl, 4 * wx, l, g, t);
            __syncthreads();
        }

        // ---- epilogue 3: masked relu -> Ps (stride 132), segment pooling ----
        #pragma unroll
        for (int mbl = 0; mbl < 4; ++mbl) {
            const int m = 64 * wy + 16 * mbl + g;
            const float mk0 = maskS[m], mk1 = maskS[m + 8];
            #pragma unroll
            for (int ntl = 0; ntl < 4; ++ntl) {
                const int n0 = (4 * wx + ntl) * 8 + 2 * t;
                const float bb0 = __ldg(b3 + n0), bb1 = __ldg(b3 + n0 + 1);
                const float p00 = mk0 * fmaxf(acc3[mbl][ntl][0] + bb0, 0.f);
                const float p01 = mk0 * fmaxf(acc3[mbl][ntl][1] + bb1, 0.f);
                const float p10 = mk1 * fmaxf(acc3[mbl][ntl][2] + bb0, 0.f);
                const float p11 = mk1 * fmaxf(acc3[mbl][ntl][3] + bb1, 0.f);
                sts64(sb + (uint32_t)((m * 132 + n0) * 4),
                      __float_as_uint(p00), __float_as_uint(p01));
                sts64(sb + (uint32_t)(((m + 8) * 132 + n0) * 4),
                      __float_as_uint(p10), __float_as_uint(p11));
            }
        }
        __syncthreads();
        for (int idx = tid; idx < 384; idx += 256) {
            const int j = idx >> 7, c = idx & 127;
            if (b0 + j < NB) {
                float s = 0.f;
                const float* base = Ps + (size_t)(37 * j) * 132 + c;
                #pragma unroll 37
                for (int ss2 = 0; ss2 < 37; ++ss2) s += base[ss2 * 132];
                g_summed[(size_t)(b0 + j) * NE + c] = s;
            }
        }
        __syncthreads();
    }
}

// ===========================================================================
// Kernel 2: fp16 tensorized actor + value heads. 64 rows/CTA, grid 256.
// ===========================================================================
__global__ void __launch_bounds__(256, 1)
head_tc(const float* __restrict__ obs,
        const float* __restrict__ ab1, const float* __restrict__ ab2,
        const float* __restrict__ aW3, const float* __restrict__ ab3,
        const float* __restrict__ vb1, const float* __restrict__ vb2,
        const float* __restrict__ vW3, const float* __restrict__ vb3,
        float* __restrict__ out)
{
    extern __shared__ float sm[];
    const int tid = threadIdx.x;
    const int w = tid >> 5, l = tid & 31;
    const int g = l >> 2, t = l & 3;
    const int wy = w >> 2, wx = w & 3;
    const uint32_t sb = smem_u32(sm);
    const uint32_t HC = sb;                 // cat frag
    const uint32_t HH = sb + HOFF_HH;       // H frag / aW3 plain
    const uint32_t HB = sb + HOFF_B;        // B bufs
    const uint32_t P_B = sb + HOFF_P;       // H2 plain
    float* Wa3 = sm + (HOFF_HH / 4);
    float* Pp  = sm + (HOFF_P / 4);
    const int m0 = blockIdx.x * 64;

    // ---- stage cat = [summed(128)|own(9)|0...] into frag (K=160) ----
    {
        const int r = tid >> 2;             // 0..63
        const int part = tid & 3;           // 40 cols each (even-aligned)
        const int row = m0 + r;
        const int mb = r >> 4, rr = r & 15, rg = rr & 7, hi8 = rr >> 3;
        for (int c = part * 40; c < part * 40 + 40; c += 2) {
            float e = 0.f, o = 0.f;
            if (c < NE)             e = g_summed[(size_t)row * NE + c];
            else if (c < NE + NOWN) e = __ldg(&obs[(size_t)row * 38 * NF + (c - NE)]);
            const int c1 = c + 1;
            if (c1 < NE)             o = g_summed[(size_t)row * NE + c1];
            else if (c1 < NE + NOWN) o = __ldg(&obs[(size_t)row * 38 * NF + (c1 - NE)]);
            const int kb16 = c >> 4, p = (c & 15) >> 1;
            const int lane = 4 * rg + (p & 3);
            const int ws = (p >> 2) * 2 + hi8;
            STS32(HC + (uint32_t)((kb16 * 4 + mb) * 512 + lane * 16 + ws * 4),
                  packh2(e, o));
        }
    }
    stageh<256>(HB, g_aW1h, 0, tid);
    CP_COMMIT();
    __syncthreads();

    float acc[2][8][4];

    // ================= actor MLP (L1+L2) ==================================
    head_mlp2(HC, HH, HB, g_aW1h, ab1, g_aW2h, acc, tid, wy, wx, l, g, t);
    epi2P(acc, ab2, P_B, wy, wx, g, t);
    __syncthreads();

    // stage aW3 plain into H region; prefetch vW1 chunk 0
    for (int e = tid; e < 256 * NOUT; e += 256)
        STS32(HH + (uint32_t)e * 4u, __float_as_uint(__ldg(&aW3[e])));
    stageh<256>(HB, g_vW1h, 0, tid);
    CP_COMMIT();
    __syncthreads();

    // ---- logits (fp32 scalar): rows w + 8i, lane = output idx ----
    if (l < NOUT) {
        float accL[8];
        const float bb = __ldg(&ab3[l]);
        #pragma unroll
        for (int i = 0; i < 8; ++i) accL[i] = bb;
        for (int k = 0; k < 256; k += 4) {
            const float wv0 = Wa3[(k + 0) * NOUT + l];
            const float wv1 = Wa3[(k + 1) * NOUT + l];
            const float wv2 = Wa3[(k + 2) * NOUT + l];
            const float wv3 = Wa3[(k + 3) * NOUT + l];
            #pragma unroll
            for (int i = 0; i < 8; ++i) {
                const float4 h = *(const float4*)(Pp + (w + 8 * i) * 260 + k);
                accL[i] += h.x * wv0 + h.y * wv1 + h.z * wv2 + h.w * wv3;
            }
        }
        #pragma unroll
        for (int i = 0; i < 8; ++i)
            out[(size_t)(m0 + w + 8 * i) * NOUT + l] = accL[i];
    }
    __syncthreads();

    // ================= value MLP (L1+L2) ==================================
    head_mlp2(HC, HH, HB, g_vW1h, vb1, g_vW2h, acc, tid, wy, wx, l, g, t);
    epi2P(acc, vb2, P_B, wy, wx, g, t);
    __syncthreads();

    // ---- value (fp32 scalar dot + warp reduce): rows w + 8i ----
    {
        float accV[8];
        #pragma unroll
        for (int i = 0; i < 8; ++i) accV[i] = 0.f;
        for (int k = l; k < 256; k += 32) {
            const float wv = __ldg(&vW3[k]);
            #pragma unroll
            for (int i = 0; i < 8; ++i)
                accV[i] += Pp[(w + 8 * i) * 260 + k] * wv;
        }
        #pragma unroll
        for (int off = 16; off; off >>= 1) {
            #pragma unroll
            for (int i = 0; i < 8; ++i)
                accV[i] += __shfl_xor_sync(0xffffffffu, accV[i], off);
        }
        if (l == 0) {
            const float bb = __ldg(&vb3[0]);
            #pragma unroll
            for (int i = 0; i < 8; ++i)
                out[(size_t)NB * NOUT + m0 + w + 8 * i] = accV[i] + bb;
        }
    }
}

// ===========================================================================
extern "C" void kernel_launch(void* const* d_in, const int* in_sizes, int n_in,
                              void* d_out, int out_size)
{
    const float* obs = (const float*)d_in[0];
    const float* sW1 = (const float*)d_in[1];
    const float* sb1 = (const float*)d_in[2];
    const float* sW2 = (const float*)d_in[3];
    const float* sb2 = (const float*)d_in[4];
    const float* sW3 = (const float*)d_in[5];
    const float* sb3 = (const float*)d_in[6];
    const float* aW1 = (const float*)d_in[7];
    const float* ab1 = (const float*)d_in[8];
    const float* aW2 = (const float*)d_in[9];
    const float* ab2 = (const float*)d_in[10];
    const float* aW3 = (const float*)d_in[11];
    const float* ab3 = (const float*)d_in[12];
    const float* vW1 = (const float*)d_in[13];
    const float* vb1 = (const float*)d_in[14];
    const float* vW2 = (const float*)d_in[15];
    const float* vb2 = (const float*)d_in[16];
    const float* vW3 = (const float*)d_in[17];
    const float* vb3 = (const float*)d_in[18];
    float* out = (float*)d_out;

    cudaFuncSetAttribute(seq_tc,  cudaFuncAttributeMaxDynamicSharedMemorySize, SMEM_TC);
    cudaFuncSetAttribute(head_tc, cudaFuncAttributeMaxDynamicSharedMemorySize, SMEM_HD);

    round_weights<<<128, 256>>>(sW1, sW2, sW3, aW1, aW2, vW1, vW2);
    seq_tc<<<152, 256, SMEM_TC>>>(obs, sb1, sb2, sb3);
    head_tc<<<NB / 64, 256, SMEM_HD>>>(obs, ab1, ab2, aW3, ab3,
                                       vb1, vb2, vW3, vb3, out);
}